// round 11
// baseline (speedup 1.0000x reference)
#include <cuda_runtime.h>
#include <cstdint>
#include <cstring>
#include <cmath>
#include <cstdio>

// ============================================================================
// np.random.default_rng(42): DIRECT raw PCG64 state (verified R8-R10).
// ============================================================================
#define MAXOPS 64
struct OpsParam {
    int n;
    int type[MAXOPS];
    int a[MAXOPS];
    int b[MAXOPS];
    int c[MAXOPS];
};

typedef unsigned __int128 hu128;

struct Pcg {
    hu128 state, inc;
    int alg, out_mode;
    int has32;
    uint32_t buf32;

    static hu128 defmul() {
        return (((hu128)0x2360ed051fc65da4ULL) << 64) | 0x4385df649fccf645ULL;
    }
    void stepv() {
        if (alg == 0) state = state * defmul() + inc;
        else          state = state * (hu128)0xda942042e4dd58b5ULL + inc;
    }
    uint64_t out_xslrr() const {
        uint64_t hi = (uint64_t)(state >> 64);
        uint64_t lo = (uint64_t)state;
        uint64_t x = hi ^ lo;
        unsigned rot = (unsigned)(state >> 122);
        return (x >> rot) | (x << ((64u - rot) & 63u));
    }
    uint64_t out_dxsm() const {
        uint64_t hi = (uint64_t)(state >> 64);
        uint64_t lo = (uint64_t)state | 1ULL;
        hi ^= hi >> 32;
        hi *= 0xda942042e4dd58b5ULL;
        hi ^= hi >> 48;
        hi *= lo;
        return hi;
    }
    uint64_t outv() const { return alg == 0 ? out_xslrr() : out_dxsm(); }
    uint64_t next64() {
        if (out_mode == 0) { stepv(); return outv(); }
        uint64_t r = outv(); stepv(); return r;
    }
    uint32_t next32() {
        if (has32) { has32 = 0; return buf32; }
        uint64_t n = next64();
        has32 = 1;
        buf32 = (uint32_t)(n >> 32);
        return (uint32_t)(n & 0xffffffffu);
    }
    double next_double() {
        return (double)(next64() >> 11) * (1.0 / 9007199254740992.0);
    }
    uint32_t lemire32(uint32_t rng) {
        uint32_t rng_excl = rng + 1u;
        uint64_t m = (uint64_t)next32() * (uint64_t)rng_excl;
        uint32_t leftover = (uint32_t)m;
        if (leftover < rng_excl) {
            uint32_t threshold = (uint32_t)((0xFFFFFFFFu - rng) % rng_excl);
            while (leftover < threshold) {
                m = (uint64_t)next32() * (uint64_t)rng_excl;
                leftover = (uint32_t)m;
            }
        }
        return (uint32_t)(m >> 32);
    }
    uint64_t random_interval(uint64_t mx) {
        if (mx == 0) return 0;
        uint64_t mask = mx;
        mask |= mask >> 1;  mask |= mask >> 2;  mask |= mask >> 4;
        mask |= mask >> 8;  mask |= mask >> 16; mask |= mask >> 32;
        uint64_t value;
        while ((value = ((uint64_t)next32() & mask)) > mx) {}
        return value;
    }
};

static hu128 parse_dec128(const char* s) {
    hu128 v = 0;
    for (; *s; s++) v = v * 10 + (hu128)(uint32_t)(*s - '0');
    return v;
}
static const char* S42_DEC = "274674114334540486603088602300644985544";
static const char* I42_DEC = "332724090758049132448979897138935081983";

static void seed_direct(Pcg& r, int alg, int out_mode) {
    r.alg = alg;
    r.out_mode = out_mode;
    r.state = parse_dec128(S42_DEC);
    r.inc   = parse_dec128(I42_DEC);
    r.has32 = 0;
    r.buf32 = 0;
}

static int find_rng(int& alg, int& om) {
    const double A0 = 0.7739560485559633;
    const double A1 = 0.4388784397520523;
    for (int a = 0; a < 2; a++)
        for (int m = 0; m < 2; m++) {
            Pcg r;
            seed_direct(r, a, m);
            double d0 = r.next_double();
            double d1 = r.next_double();
            if (fabs(d0 - A0) < 1e-9 && fabs(d1 - A1) < 1e-9) { alg = a; om = m; return 1; }
        }
    return 0;
}

static int build_ops(OpsParam& ops) {
    int alg, om;
    if (!find_rng(alg, om)) {
        fputs("DIAG rng core verification failed\n", stderr);
        fflush(stderr);
        return 0;
    }
    Pcg rng;
    seed_direct(rng, alg, om);

    ops.n = 0;
    int i = 0;
    while (i < 4 && ops.n < MAXOPS) {
        if (rng.next_double() > 0.3) {
            int kind = (int)rng.lemire32(2);
            int w    = (int)rng.lemire32(3);
            ops.type[ops.n] = 0; ops.a[ops.n] = kind; ops.b[ops.n] = w; ops.c[ops.n] = i;
            ops.n++; i++;
        } else {
            int arr[4] = {0, 1, 2, 3};
            for (int t = 3; t >= 1; t--) {
                int j = (int)rng.random_interval((uint64_t)t);
                int tmp = arr[t]; arr[t] = arr[j]; arr[j] = tmp;
            }
            ops.type[ops.n] = 1; ops.a[ops.n] = arr[0]; ops.b[ops.n] = arr[1]; ops.c[ops.n] = 0;
            ops.n++;
        }
    }
    return 1;
}

// ============================================================================
// Shared helpers
// ============================================================================
typedef unsigned long long ull;

__device__ __forceinline__ ull pk2f(float lo, float hi) {
    ull r; asm("mov.b64 %0, {%1, %2};" : "=l"(r) : "f"(lo), "f"(hi)); return r;
}
__device__ __forceinline__ void upk2f(ull v, float& lo, float& hi) {
    asm("mov.b64 {%0, %1}, %2;" : "=f"(lo), "=f"(hi) : "l"(v));
}
__device__ __forceinline__ ull fma2_(ull a, ull b, ull c) {
    ull d; asm("fma.rn.f32x2 %0, %1, %2, %3;" : "=l"(d) : "l"(a), "l"(b), "l"(c)); return d;
}
__device__ __forceinline__ ull mul2_(ull a, ull b) {
    ull d; asm("mul.rn.f32x2 %0, %1, %2;" : "=l"(d) : "l"(a), "l"(b)); return d;
}
__device__ __forceinline__ ull add2_(ull a, ull b) {
    ull d; asm("add.rn.f32x2 %0, %1, %2;" : "=l"(d) : "l"(a), "l"(b)); return d;
}

// Pauli product (0=I,1=X,2=Y,3=Z): sigma_a*sigma_b = i^k sigma_r
__host__ __device__ __forceinline__ int pmul_h(int a, int b, int& k) {
    if (a == 0) return b;
    if (b == 0) return a;
    if (a == b) return 0;
    int r = 6 - a - b;
    k += (b == (a % 3) + 1) ? 1 : 3;
    return r;
}

// ============================================================================
// FUSED SPARSE KERNEL (host provides structural term list via const masks)
// ============================================================================
#define KMAX 32
struct GateList {
    int n;
    int typ[16];
    int p1[16];
    int p2[16];
    int p3[16];
};
struct TermParam {
    int K;
    int mono[KMAX];      // monomial index (0..80) for tab lookup
    ull mC[KMAX][4];     // per-term/per-wire 64-bit select masks
    ull mS[KMAX][4];
    ull mOne[KMAX][4];
};

// Host-side structural propagation: which monomials can appear?
static int host_terms(const OpsParam& ops, int* mono_out) {
    bool live[81];
    for (int m = 0; m < 81; m++) live[m] = false;
    for (int w = 0; w < 4; w++) {
        for (int path = 0; path < 16; path++) {
            int lets = 3 << (2 * w);
            bool dead = false;
            int rbit = 0;
            for (int g = ops.n - 1; g >= 0 && !dead; g--) {
                if (ops.type[g] == 0) {
                    int P = ops.a[g] + 1;
                    int wi = ops.b[g];
                    int q = (lets >> (2 * wi)) & 3;
                    int take = (path >> rbit) & 1;
                    rbit++;
                    if (q == 0 || q == P) {
                        if (take) dead = true;
                    } else if (take) {
                        int r = 6 - P - q;
                        lets = (lets & ~(3 << (2 * wi))) | (r << (2 * wi));
                    }
                } else {
                    int c = ops.a[g], tt = ops.b[g];
                    int a = (lets >> (2 * c)) & 3;
                    int bb = (lets >> (2 * tt)) & 3;
                    int At = (a == 1 || a == 2) ? 1 : 0;
                    int Bc2 = (bb == 2 || bb == 3) ? 3 : 0;
                    int k = 0;
                    int nc = pmul_h(a, Bc2, k);
                    int nt = pmul_h(At, bb, k);
                    lets = (lets & ~((3 << (2 * c)) | (3 << (2 * tt))))
                         | (nc << (2 * c)) | (nt << (2 * tt));
                }
            }
            if (dead) continue;
            int e[4], ok = 1;
            for (int wi = 0; wi < 4; wi++) {
                int L = (lets >> (2 * wi)) & 3;
                if (L == 2) { ok = 0; break; }
                e[wi] = (L == 0) ? 0 : ((L == 3) ? 1 : 2);
            }
            if (ok) live[(e[0] * 3 + e[1]) * 9 + (e[2] * 3 + e[3])] = true;
        }
    }
    int K = 0;
    for (int m = 0; m < 81; m++)
        if (live[m]) mono_out[K++] = m;
    return K;
}

template <int KPAD>
__global__ void __launch_bounds__(512, 3) quanv_fused(const float* __restrict__ rp,
                                                      const float4* __restrict__ x4,
                                                      float4* __restrict__ out4,
                                                      GateList gl, TermParam tp) {
    __shared__ float tab[81][4];
    __shared__ int   e_m[64];
    __shared__ float e_c[64];
    __shared__ ull   s_cd[KMAX][4];

    const int tx = threadIdx.x;

    // ---- issue global input loads EARLY ----
    int tid = blockIdx.x * 512 + tx;
    int t = tid & 15;
    int j = (tid >> 4) & 31;
    int i = (tid >> 9) & 31;
    int b = tid >> 14;
    int r00 = ((b * 64 + 2 * i) * 64 + 2 * j) * 16 + t;
    float4 f00 = x4[r00];
    float4 f01 = x4[r00 + 16];
    float4 f10 = x4[r00 + 1024];
    float4 f11 = x4[r00 + 1040];

    if (tx < 324) ((float*)tab)[tx] = 0.0f;

    // ---- Pauli back-propagation with real thetas: 4 wires x 16 paths ----
    if (tx < 64) {
        int w = tx >> 4, path = tx & 15;
        int lets = 3 << (2 * w);
        float coef = 1.0f;
        int rbit = 0;
        for (int g = gl.n - 1; g >= 0; g--) {
            if (gl.typ[g] == 0) {
                int P = gl.p1[g] + 1;
                int wi = gl.p2[g];
                int q = (lets >> (2 * wi)) & 3;
                int take = (path >> rbit) & 1;
                rbit++;
                if (q == 0 || q == P) {
                    if (take) coef = 0.0f;
                } else {
                    float th = rp[gl.p3[g]];
                    if (!take) {
                        coef *= cosf(th);
                    } else {
                        coef *= sinf(th);
                        int r = 6 - P - q;
                        int qp = (P == 1) ? 3 : P - 1;
                        coef = (q == qp) ? coef : -coef;
                        lets = (lets & ~(3 << (2 * wi))) | (r << (2 * wi));
                    }
                }
            } else {
                int c = gl.p1[g], tt = gl.p2[g];
                int a = (lets >> (2 * c)) & 3;
                int bb = (lets >> (2 * tt)) & 3;
                int At = (a == 1 || a == 2) ? 1 : 0;
                int Bc2 = (bb == 2 || bb == 3) ? 3 : 0;
                int k = 0;
                int nc = pmul_h(a, Bc2, k);
                int nt = pmul_h(At, bb, k);
                if ((k & 3) == 2) coef = -coef;
                lets = (lets & ~((3 << (2 * c)) | (3 << (2 * tt))))
                     | (nc << (2 * c)) | (nt << (2 * tt));
            }
        }
        int m = -1;
        if (coef != 0.0f) {
            int e[4], ok = 1;
            for (int wi = 0; wi < 4; wi++) {
                int L = (lets >> (2 * wi)) & 3;
                if (L == 2) { ok = 0; break; }
                e[wi] = (L == 0) ? 0 : ((L == 3) ? 1 : 2);
            }
            if (ok) m = (e[0] * 3 + e[1]) * 9 + (e[2] * 3 + e[3]);
        }
        e_m[tx] = m;
        e_c[tx] = coef;
    }
    __syncthreads();

    // ---- deterministic merge ----
    if (tx < 4) {
        for (int k = 0; k < 16; k++) {
            int m = e_m[tx * 16 + k];
            if (m >= 0) tab[m][tx] += e_c[tx * 16 + k];
        }
    }
    __syncthreads();

    // ---- fill coef table in HOST-provided order (no ballot) ----
    if (tx < KPAD) {
        for (int w = 0; w < 4; w++) {
            float c = (tx < tp.K) ? tab[tp.mono[tx]][w] : 0.0f;
            uint32_t u = __float_as_uint(c);
            s_cd[tx][w] = (ull)u | ((ull)u << 32);
        }
    }
    __syncthreads();

    // ---- per-sample trig ----
    const float PI = 3.14159265358979323846f;
    float s0, c0, s1, c1;
    ull C0, S0, C1, S1, C2, S2, C3, S3;
    __sincosf(PI * f00.x, &s0, &c0); __sincosf(PI * f00.z, &s1, &c1);
    C0 = pk2f(c0, c1); S0 = pk2f(s0, s1);
    __sincosf(PI * f11.x, &s0, &c0); __sincosf(PI * f11.z, &s1, &c1);
    C1 = pk2f(c0, c1); S1 = pk2f(s0, s1);
    __sincosf(PI * f01.y, &s0, &c0); __sincosf(PI * f01.w, &s1, &c1);
    C2 = pk2f(c0, c1); S2 = pk2f(s0, s1);
    __sincosf(PI * f10.y, &s0, &c0); __sincosf(PI * f10.w, &s1, &c1);
    C3 = pk2f(c0, c1); S3 = pk2f(s0, s1);

    ull acc0 = 0, acc1 = 0, acc2 = 0, acc3 = 0;

#pragma unroll
    for (int k = 0; k < KPAD; k++) {
        // factors via const-bank masks: (C & mC) | (S & mS) | mOne
        ull g0 = (C0 & tp.mC[k][0]) | (S0 & tp.mS[k][0]) | tp.mOne[k][0];
        ull g1 = (C1 & tp.mC[k][1]) | (S1 & tp.mS[k][1]) | tp.mOne[k][1];
        ull g2 = (C2 & tp.mC[k][2]) | (S2 & tp.mS[k][2]) | tp.mOne[k][2];
        ull g3 = (C3 & tp.mC[k][3]) | (S3 & tp.mS[k][3]) | tp.mOne[k][3];
        ull u = mul2_(mul2_(g0, g1), mul2_(g2, g3));
        acc0 = fma2_(u, s_cd[k][0], acc0);
        acc1 = fma2_(u, s_cd[k][1], acc1);
        acc2 = fma2_(u, s_cd[k][2], acc2);
        acc3 = fma2_(u, s_cd[k][3], acc3);
    }

    float a0l, a0h, a1l, a1h, a2l, a2h, a3l, a3h;
    upk2f(acc0, a0l, a0h); upk2f(acc1, a1l, a1h);
    upk2f(acc2, a2l, a2h); upk2f(acc3, a3l, a3h);
    out4[2 * tid]     = make_float4(a0l, a1l, a2l, a3l);
    out4[2 * tid + 1] = make_float4(a0h, a1h, a2h, a3h);
}

// ============================================================================
// DENSE FALLBACK (exact R8 kernels — proven correct)
// ============================================================================
__device__ float4 g_coef4[162];

__device__ __forceinline__ float2 cmulf(float2 a, float2 b) {
    return make_float2(a.x * b.x - a.y * b.y, a.x * b.y + a.y * b.x);
}
__device__ __forceinline__ float2 caddf(float2 a, float2 b) {
    return make_float2(a.x + b.x, a.y + b.y);
}
__device__ __forceinline__ float Bc(int jb, int kb, int e) {
    if (jb != kb) return (e == 2) ? 0.5f : 0.0f;
    if (e == 2) return 0.0f;
    if (e == 0) return 0.5f;
    return jb ? -0.5f : 0.5f;
}

__global__ void quanv_setup(const float* __restrict__ rp, OpsParam ops) {
    __shared__ float2 U[16][16];
    __shared__ float ReM[4][16][16];
    __shared__ float G[4][9][16];
    int tid = threadIdx.x;

    if (tid < 16) {
        int col = tid;
        for (int m = 0; m < 16; m++)
            U[m][col] = make_float2(m == col ? 1.0f : 0.0f, 0.0f);
        for (int o = 0; o < ops.n; o++) {
            if (ops.type[o] == 0) {
                float th = rp[ops.c[o]];
                float ch = cosf(0.5f * th), sh = sinf(0.5f * th);
                float2 R00, R01, R10, R11;
                int kind = ops.a[o];
                if (kind == 0) {
                    R00 = make_float2(ch, 0); R11 = R00;
                    R01 = make_float2(0, -sh); R10 = R01;
                } else if (kind == 1) {
                    R00 = make_float2(ch, 0); R11 = R00;
                    R01 = make_float2(-sh, 0); R10 = make_float2(sh, 0);
                } else {
                    R00 = make_float2(ch, -sh); R11 = make_float2(ch, sh);
                    R01 = make_float2(0, 0);    R10 = make_float2(0, 0);
                }
                int bit = 1 << (3 - ops.b[o]);
                for (int m = 0; m < 16; m++) {
                    if (!(m & bit)) {
                        float2 x0 = U[m][col], x1 = U[m | bit][col];
                        U[m][col]       = caddf(cmulf(R00, x0), cmulf(R01, x1));
                        U[m | bit][col] = caddf(cmulf(R10, x0), cmulf(R11, x1));
                    }
                }
            } else {
                int cb = 1 << (3 - ops.a[o]);
                int tb = 1 << (3 - ops.b[o]);
                for (int m = 0; m < 16; m++) {
                    if ((m & cb) && !(m & tb)) {
                        float2 tmp = U[m][col];
                        U[m][col] = U[m | tb][col];
                        U[m | tb][col] = tmp;
                    }
                }
            }
        }
    }
    __syncthreads();

    for (int e = tid; e < 1024; e += blockDim.x) {
        int w = e >> 8, jk = e & 255, jj = jk >> 4, kk = jk & 15;
        int sbit = 1 << (3 - w);
        float sum = 0.0f;
        for (int m = 0; m < 16; m++) {
            float2 uj = U[m][jj], uk = U[m][kk];
            float re = uj.x * uk.x + uj.y * uk.y;
            sum += (m & sbit) ? -re : re;
        }
        ReM[w][jj][kk] = sum;
    }
    __syncthreads();

    for (int e = tid; e < 576; e += blockDim.x) {
        int w = e / 144, r = e % 144, p = r / 16, lk = r % 16;
        int jl = lk >> 2, kl = lk & 3;
        int e0 = p / 3, e1 = p % 3;
        float sum = 0.0f;
        for (int jh = 0; jh < 4; jh++)
            for (int kh = 0; kh < 4; kh++) {
                float w01 = Bc(jh >> 1, kh >> 1, e0) * Bc(jh & 1, kh & 1, e1);
                if (w01 != 0.0f)
                    sum += w01 * ReM[w][jh * 4 + jl][kh * 4 + kl];
            }
        G[w][p][lk] = sum;
    }
    __syncthreads();

    for (int m = tid; m < 81; m += blockDim.x) {
        int p = m / 9, q = m % 9;
        int e2 = q / 3, e3 = q % 3;
        float cw[4];
        for (int w = 0; w < 4; w++) {
            float sum = 0.0f;
            for (int jl = 0; jl < 4; jl++)
                for (int kl = 0; kl < 4; kl++) {
                    float w23 = Bc(jl >> 1, kl >> 1, e2) * Bc(jl & 1, kl & 1, e3);
                    if (w23 != 0.0f)
                        sum += w23 * G[w][p][jl * 4 + kl];
                }
            cw[w] = sum;
        }
        g_coef4[2 * m]     = make_float4(cw[0], cw[0], cw[1], cw[1]);
        g_coef4[2 * m + 1] = make_float4(cw[2], cw[2], cw[3], cw[3]);
    }
}

__global__ void __launch_bounds__(256) quanv_main(const float4* __restrict__ x4,
                                                  float4* __restrict__ out4) {
    __shared__ ulonglong2 shc[162];
    if (threadIdx.x < 162) {
        const ulonglong2* gc = reinterpret_cast<const ulonglong2*>(g_coef4);
        shc[threadIdx.x] = gc[threadIdx.x];
    }
    __syncthreads();

    int tid = blockIdx.x * 256 + threadIdx.x;
    int t = tid & 15;
    int j = (tid >> 4) & 31;
    int i = (tid >> 9) & 31;
    int b = tid >> 14;

    int r00 = ((b * 64 + 2 * i) * 64 + 2 * j) * 16 + t;
    float4 f00 = __ldcs(&x4[r00]);
    float4 f01 = __ldcs(&x4[r00 + 16]);
    float4 f10 = __ldcs(&x4[r00 + 1024]);
    float4 f11 = __ldcs(&x4[r00 + 1040]);

    const float PI = 3.14159265358979323846f;
    float s0, c0, s1, c1;
    ull C0, S0, C1, S1, C2, S2, C3, S3;
    __sincosf(PI * f00.x, &s0, &c0); __sincosf(PI * f00.z, &s1, &c1);
    C0 = pk2f(c0, c1); S0 = pk2f(s0, s1);
    __sincosf(PI * f11.x, &s0, &c0); __sincosf(PI * f11.z, &s1, &c1);
    C1 = pk2f(c0, c1); S1 = pk2f(s0, s1);
    __sincosf(PI * f01.y, &s0, &c0); __sincosf(PI * f01.w, &s1, &c1);
    C2 = pk2f(c0, c1); S2 = pk2f(s0, s1);
    __sincosf(PI * f10.y, &s0, &c0); __sincosf(PI * f10.w, &s1, &c1);
    C3 = pk2f(c0, c1); S3 = pk2f(s0, s1);

    ull v01[9], v23[9];
    v01[0] = 0; v23[0] = 0;
    v01[1] = C1; v01[2] = S1; v01[3] = C0;
    v01[4] = mul2_(C0, C1); v01[5] = mul2_(C0, S1);
    v01[6] = S0; v01[7] = mul2_(S0, C1); v01[8] = mul2_(S0, S1);
    v23[1] = C3; v23[2] = S3; v23[3] = C2;
    v23[4] = mul2_(C2, C3); v23[5] = mul2_(C2, S3);
    v23[6] = S2; v23[7] = mul2_(S2, C3); v23[8] = mul2_(S2, S3);

    ull acc0 = 0, acc1 = 0, acc2 = 0, acc3 = 0;

#pragma unroll
    for (int p = 0; p < 9; p++) {
#pragma unroll
        for (int q = 0; q < 9; q++) {
            int m = p * 9 + q;
            ulonglong2 ca = shc[2 * m];
            ulonglong2 cb = shc[2 * m + 1];
            if (p == 0 && q == 0) {
                acc0 = add2_(acc0, ca.x);
                acc1 = add2_(acc1, ca.y);
                acc2 = add2_(acc2, cb.x);
                acc3 = add2_(acc3, cb.y);
            } else {
                ull tpq = (p == 0) ? v23[q] : ((q == 0) ? v01[p] : mul2_(v01[p], v23[q]));
                acc0 = fma2_(tpq, ca.x, acc0);
                acc1 = fma2_(tpq, ca.y, acc1);
                acc2 = fma2_(tpq, cb.x, acc2);
                acc3 = fma2_(tpq, cb.y, acc3);
            }
        }
    }

    float a0l, a0h, a1l, a1h, a2l, a2h, a3l, a3h;
    upk2f(acc0, a0l, a0h); upk2f(acc1, a1l, a1h);
    upk2f(acc2, a2l, a2h); upk2f(acc3, a3l, a3h);
    out4[2 * tid]     = make_float4(a0l, a1l, a2l, a3l);
    out4[2 * tid + 1] = make_float4(a0h, a1h, a2h, a3h);
}

// ============================================================================
// Launch
// ============================================================================
extern "C" void kernel_launch(void* const* d_in, const int* in_sizes, int n_in,
                              void* d_out, int out_size) {
    const float* x  = (const float*)d_in[0];
    const float* rp = (const float*)d_in[1];
    if (n_in >= 2 && in_sizes[0] == 4) {
        const float* tmp = x; x = rp; rp = tmp;
    }

    OpsParam ops;
    if (!build_ops(ops)) return;

    int nrot = 0;
    for (int o = 0; o < ops.n; o++)
        if (ops.type[o] == 0) nrot++;

    int mono[81];
    int K = (nrot == 4 && ops.n <= 16) ? host_terms(ops, mono) : 1000;

    if (K <= KMAX) {
        GateList gl;
        gl.n = ops.n;
        for (int o = 0; o < ops.n; o++) {
            gl.typ[o] = ops.type[o];
            gl.p1[o] = ops.a[o];
            gl.p2[o] = ops.b[o];
            gl.p3[o] = ops.c[o];
        }
        for (int o = ops.n; o < 16; o++) { gl.typ[o] = 0; gl.p1[o] = 0; gl.p2[o] = 0; gl.p3[o] = 0; }

        TermParam tp;
        memset(&tp, 0, sizeof(tp));
        tp.K = K;
        const ull ONE2 = 0x3f8000003f800000ULL;
        const ull FULL = 0xffffffffffffffffULL;
        for (int k = 0; k < KMAX; k++) {
            int m = (k < K) ? mono[k] : 0;
            tp.mono[k] = m;
            int e[4] = { m / 27, (m / 9) % 3, (m / 3) % 3, m % 3 };
            for (int w = 0; w < 4; w++) {
                if (k >= K || e[w] == 0) { tp.mOne[k][w] = ONE2; }
                else if (e[w] == 1)      { tp.mC[k][w] = FULL; }
                else                     { tp.mS[k][w] = FULL; }
            }
        }

        const float4* x4 = (const float4*)x;
        float4* o4 = (float4*)d_out;
        if (K <= 8)       quanv_fused<8><<<512, 512>>>(rp, x4, o4, gl, tp);
        else if (K <= 16) quanv_fused<16><<<512, 512>>>(rp, x4, o4, gl, tp);
        else if (K <= 24) quanv_fused<24><<<512, 512>>>(rp, x4, o4, gl, tp);
        else              quanv_fused<32><<<512, 512>>>(rp, x4, o4, gl, tp);
    } else {
        quanv_setup<<<1, 512>>>(rp, ops);
        quanv_main<<<1024, 256>>>((const float4*)x, (float4*)d_out);
    }
}

// round 12
// speedup vs baseline: 1.4060x; 1.4060x over previous
#include <cuda_runtime.h>
#include <cstdint>
#include <cstring>
#include <cstdio>

// ============================================================================
// Portable 128-bit (constexpr-safe, no __int128)
// ============================================================================
struct U128 { uint64_t hi, lo; };

constexpr U128 u128_mul64(uint64_t a, uint64_t b) {
    uint64_t a0 = a & 0xffffffffULL, a1 = a >> 32;
    uint64_t b0 = b & 0xffffffffULL, b1 = b >> 32;
    uint64_t p00 = a0 * b0, p01 = a0 * b1, p10 = a1 * b0, p11 = a1 * b1;
    uint64_t mid = (p00 >> 32) + (p01 & 0xffffffffULL) + (p10 & 0xffffffffULL);
    uint64_t lo = (p00 & 0xffffffffULL) | (mid << 32);
    uint64_t hi = p11 + (p01 >> 32) + (p10 >> 32) + (mid >> 32);
    return {hi, lo};
}
constexpr U128 u128_mul(U128 a, U128 b) {
    U128 ll = u128_mul64(a.lo, b.lo);
    return {ll.hi + a.lo * b.hi + a.hi * b.lo, ll.lo};
}
constexpr U128 u128_add(U128 a, U128 b) {
    uint64_t lo = a.lo + b.lo;
    return {a.hi + b.hi + (lo < a.lo ? 1u : 0u), lo};
}
constexpr U128 u128_shl1_or1(U128 a) {
    return {(a.hi << 1) | (a.lo >> 63), (a.lo << 1) | 1ULL};
}
constexpr U128 parse_dec128(const char* s) {
    U128 v{0, 0};
    for (; *s; s++) {
        v = u128_mul(v, U128{0, 10});
        v = u128_add(v, U128{0, (uint64_t)(*s - '0')});
    }
    return v;
}

// ============================================================================
// np.random.default_rng(42): direct raw PCG64 state (HW-verified R8-R11).
// Fully constexpr so gate structure becomes compile-time constants.
// ============================================================================
struct PcgCx {
    U128 state{0, 0}, inc{0, 0};
    int alg = 0, out_mode = 0;
    int has32 = 0;
    uint32_t buf32 = 0;

    constexpr void stepv() {
        if (alg == 0)
            state = u128_add(u128_mul(state, U128{0x2360ed051fc65da4ULL, 0x4385df649fccf645ULL}), inc);
        else
            state = u128_add(u128_mul(state, U128{0, 0xda942042e4dd58b5ULL}), inc);
    }
    constexpr uint64_t out_xslrr() const {
        uint64_t x = state.hi ^ state.lo;
        unsigned rot = (unsigned)(state.hi >> 58);
        return (x >> rot) | (x << ((64u - rot) & 63u));
    }
    constexpr uint64_t out_dxsm() const {
        uint64_t hi = state.hi, lo = state.lo | 1ULL;
        hi ^= hi >> 32; hi *= 0xda942042e4dd58b5ULL;
        hi ^= hi >> 48; hi *= lo;
        return hi;
    }
    constexpr uint64_t next64() {
        if (out_mode == 0) { stepv(); return alg == 0 ? out_xslrr() : out_dxsm(); }
        uint64_t r = alg == 0 ? out_xslrr() : out_dxsm();
        stepv();
        return r;
    }
    constexpr uint32_t next32() {
        if (has32) { has32 = 0; return buf32; }
        uint64_t n = next64();
        has32 = 1;
        buf32 = (uint32_t)(n >> 32);
        return (uint32_t)(n & 0xffffffffu);
    }
    constexpr double next_double() {
        return (double)(next64() >> 11) * (1.0 / 9007199254740992.0);
    }
    constexpr uint32_t lemire32(uint32_t rng) {
        uint32_t rng_excl = rng + 1u;
        uint64_t m = (uint64_t)next32() * (uint64_t)rng_excl;
        uint32_t leftover = (uint32_t)m;
        if (leftover < rng_excl) {
            uint32_t threshold = (uint32_t)((0xFFFFFFFFu - rng) % rng_excl);
            while (leftover < threshold) {
                m = (uint64_t)next32() * (uint64_t)rng_excl;
                leftover = (uint32_t)m;
            }
        }
        return (uint32_t)(m >> 32);
    }
    constexpr uint64_t random_interval(uint64_t mx) {
        if (mx == 0) return 0;
        uint64_t mask = mx;
        mask |= mask >> 1;  mask |= mask >> 2;  mask |= mask >> 4;
        mask |= mask >> 8;  mask |= mask >> 16; mask |= mask >> 32;
        uint64_t value = 0;
        while ((value = ((uint64_t)next32() & mask)) > mx) {}
        return value;
    }
};

constexpr void seed_direct_cx(PcgCx& r, int alg, int om) {
    r.alg = alg;
    r.out_mode = om;
    r.state = parse_dec128("274674114334540486603088602300644985544");
    r.inc   = parse_dec128("332724090758049132448979897138935081983");
    r.has32 = 0;
    r.buf32 = 0;
}
constexpr double dabs_cx(double x) { return x < 0 ? -x : x; }

constexpr int find_variant_cx() {
    for (int a = 0; a < 2; a++)
        for (int m = 0; m < 2; m++) {
            PcgCx r;
            seed_direct_cx(r, a, m);
            double d0 = r.next_double();
            double d1 = r.next_double();
            if (dabs_cx(d0 - 0.7739560485559633) < 1e-9 &&
                dabs_cx(d1 - 0.4388784397520523) < 1e-9)
                return a * 2 + m;
        }
    return -1;
}

#define MAXOPS 64
struct Ops4 {
    int n = 0;
    int type[MAXOPS] = {};
    int a[MAXOPS] = {};
    int b[MAXOPS] = {};
    int c[MAXOPS] = {};
};

constexpr Ops4 build_ops_cx(int variant) {
    Ops4 ops{};
    PcgCx rng;
    seed_direct_cx(rng, variant >> 1, variant & 1);
    int i = 0;
    while (i < 4 && ops.n < MAXOPS) {
        if (rng.next_double() > 0.3) {
            int kind = (int)rng.lemire32(2);
            int w    = (int)rng.lemire32(3);
            ops.type[ops.n] = 0; ops.a[ops.n] = kind; ops.b[ops.n] = w; ops.c[ops.n] = i;
            ops.n++; i++;
        } else {
            int arr[4] = {0, 1, 2, 3};
            for (int t = 3; t >= 1; t--) {
                int j = (int)rng.random_interval((uint64_t)t);
                int tmp = arr[t]; arr[t] = arr[j]; arr[j] = tmp;
            }
            ops.type[ops.n] = 1; ops.a[ops.n] = arr[0]; ops.b[ops.n] = arr[1]; ops.c[ops.n] = 0;
            ops.n++;
        }
    }
    return ops;
}

// Pauli product (0=I,1=X,2=Y,3=Z): sigma_a*sigma_b = i^k sigma_r
__host__ __device__ constexpr int pmul_h(int a, int b, int& k) {
    if (a == 0) return b;
    if (b == 0) return a;
    if (a == b) return 0;
    int r = 6 - a - b;
    k += (b == (a % 3) + 1) ? 1 : 3;
    return r;
}

// Structural term derivation (theta-independent liveness)
struct TermsCx {
    int n[4] = {};
    int ec[4][16] = {};    // e-code: e0|e1<<2|e2<<4|e3<<6, e: 0=I,1=C(Z),2=S(X)
    int mono[4][16] = {};  // tab index m = e0*27+e1*9+e2*3+e3
};

constexpr TermsCx derive_terms_cx(const Ops4& ops) {
    TermsCx t{};
    for (int w = 0; w < 4; w++) {
        for (int path = 0; path < 16; path++) {
            int lets = 3 << (2 * w);
            bool dead = false;
            int rbit = 0;
            for (int g = ops.n - 1; g >= 0 && !dead; g--) {
                if (ops.type[g] == 0) {
                    int P = ops.a[g] + 1;
                    int wi = ops.b[g];
                    int q = (lets >> (2 * wi)) & 3;
                    int take = (path >> rbit) & 1;
                    rbit++;
                    if (q == 0 || q == P) {
                        if (take) dead = true;
                    } else if (take) {
                        int r = 6 - P - q;
                        lets = (lets & ~(3 << (2 * wi))) | (r << (2 * wi));
                    }
                } else {
                    int c = ops.a[g], tt = ops.b[g];
                    int a = (lets >> (2 * c)) & 3;
                    int bb = (lets >> (2 * tt)) & 3;
                    int At = (a == 1 || a == 2) ? 1 : 0;
                    int Bc2 = (bb == 2 || bb == 3) ? 3 : 0;
                    int k = 0;
                    int nc = pmul_h(a, Bc2, k);
                    int nt = pmul_h(At, bb, k);
                    lets = (lets & ~((3 << (2 * c)) | (3 << (2 * tt))))
                         | (nc << (2 * c)) | (nt << (2 * tt));
                }
            }
            if (dead) continue;
            int e[4] = {}, ok = 1;
            for (int wi = 0; wi < 4; wi++) {
                int L = (lets >> (2 * wi)) & 3;
                if (L == 2) { ok = 0; break; }
                e[wi] = (L == 0) ? 0 : ((L == 3) ? 1 : 2);
            }
            if (!ok) continue;
            int ecb = e[0] | (e[1] << 2) | (e[2] << 4) | (e[3] << 6);
            int m = e[0] * 27 + e[1] * 9 + e[2] * 3 + e[3];
            bool found = false;
            for (int jj = 0; jj < t.n[w]; jj++)
                if (t.ec[w][jj] == ecb) { found = true; break; }
            if (!found && t.n[w] < 16) {
                t.ec[w][t.n[w]] = ecb;
                t.mono[w][t.n[w]] = m;
                t.n[w]++;
            }
        }
    }
    return t;
}

constexpr uint64_t pack8(const TermsCx& t, int w, int lohalf) {
    uint64_t v = 0;
    for (int j = 0; j < 8; j++) {
        int jj = lohalf * 8 + j;
        if (jj < t.n[w]) v |= ((uint64_t)(t.ec[w][jj] & 0xff)) << (8 * j);
    }
    return v;
}

// ---- compile-time constants ----
constexpr int   CXV  = find_variant_cx();
constexpr Ops4  CXOPS = build_ops_cx(CXV < 0 ? 0 : CXV);
constexpr TermsCx CXT = (CXV >= 0) ? derive_terms_cx(CXOPS) : TermsCx{};
constexpr int CN0 = CXT.n[0], CN1 = CXT.n[1], CN2 = CXT.n[2], CN3 = CXT.n[3];
constexpr uint64_t CA0 = pack8(CXT, 0, 0), CB0 = pack8(CXT, 0, 1);
constexpr uint64_t CA1 = pack8(CXT, 1, 0), CB1 = pack8(CXT, 1, 1);
constexpr uint64_t CA2 = pack8(CXT, 2, 0), CB2 = pack8(CXT, 2, 1);
constexpr uint64_t CA3 = pack8(CXT, 3, 0), CB3 = pack8(CXT, 3, 1);

// ============================================================================
// Device helpers
// ============================================================================
typedef unsigned long long ull;

__device__ __forceinline__ ull pk2f(float lo, float hi) {
    ull r; asm("mov.b64 %0, {%1, %2};" : "=l"(r) : "f"(lo), "f"(hi)); return r;
}
__device__ __forceinline__ void upk2f(ull v, float& lo, float& hi) {
    asm("mov.b64 {%0, %1}, %2;" : "=f"(lo), "=f"(hi) : "l"(v));
}
__device__ __forceinline__ ull fma2_(ull a, ull b, ull c) {
    ull d; asm("fma.rn.f32x2 %0, %1, %2, %3;" : "=l"(d) : "l"(a), "l"(b), "l"(c)); return d;
}
__device__ __forceinline__ ull mul2_(ull a, ull b) {
    ull d; asm("mul.rn.f32x2 %0, %1, %2;" : "=l"(d) : "l"(a), "l"(b)); return d;
}
__device__ __forceinline__ ull add2_(ull a, ull b) {
    ull d; asm("add.rn.f32x2 %0, %1, %2;" : "=l"(d) : "l"(a), "l"(b)); return d;
}

template <int EC>
__device__ __forceinline__ ull prod_ec(ull C0, ull S0, ull C1, ull S1,
                                       ull C2, ull S2, ull C3, ull S3) {
    constexpr int e0 = EC & 3, e1 = (EC >> 2) & 3, e2 = (EC >> 4) & 3, e3 = (EC >> 6) & 3;
    ull u = 0x3f8000003f800000ULL;
    if constexpr (e0 == 1) u = C0; else if constexpr (e0 == 2) u = S0;
    constexpr bool h0 = (e0 != 0);
    if constexpr (e1 != 0) { ull f = (e1 == 1) ? C1 : S1; if constexpr (h0) u = mul2_(u, f); else u = f; }
    constexpr bool h1 = h0 || (e1 != 0);
    if constexpr (e2 != 0) { ull f = (e2 == 1) ? C2 : S2; if constexpr (h1) u = mul2_(u, f); else u = f; }
    constexpr bool h2 = h1 || (e2 != 0);
    if constexpr (e3 != 0) { ull f = (e3 == 1) ? C3 : S3; if constexpr (h2) u = mul2_(u, f); else u = f; }
    return u;
}

// ============================================================================
// FUSED KERNEL (compile-time term structure)
// ============================================================================
struct GateListP {
    int n;
    int typ[24];
    int p1[24];
    int p2[24];
    int p3[24];
};
struct FillParam {
    int nt[4];
    int mono[64];
};

#define NBLK 444
#define UPB  591   // 444*591 = 262404 >= 262144 units (2 samples each)

template <int N0, int N1, int N2, int N3,
          ull A0, ull B0, ull A1, ull B1, ull A2, ull B2, ull A3, ull B3>
__global__ void __launch_bounds__(512, 3) quanv_cx(const float* __restrict__ rp,
                                                   const float4* __restrict__ x4,
                                                   float4* __restrict__ out4,
                                                   GateListP gl, FillParam fp) {
    __shared__ float tab[81][4];
    __shared__ int   e_m[64];
    __shared__ float e_c[64];
    __shared__ ull   sc[4][16];

    const int tx = threadIdx.x;
    const int ustart = blockIdx.x * UPB;
    const int uend   = min(ustart + UPB, 262144);
    const int u0 = ustart + tx;
    const bool v0 = (u0 < uend);

    // ---- early loads for unit 0 (overlap prologue latency) ----
    float4 f00, f01, f10, f11;
    if (v0) {
        int r00 = ((u0 >> 14) << 16) + (((u0 >> 9) & 31) << 11) + (((u0 >> 4) & 31) << 5) + (u0 & 15);
        f00 = x4[r00];
        f01 = x4[r00 + 16];
        f10 = x4[r00 + 1024];
        f11 = x4[r00 + 1040];
    }

    if (tx < 324) ((float*)tab)[tx] = 0.0f;

    // ---- Pauli back-propagation with runtime thetas: 4 wires x 16 paths ----
    if (tx < 64) {
        int w = tx >> 4, path = tx & 15;
        int lets = 3 << (2 * w);
        float coef = 1.0f;
        int rbit = 0;
        for (int g = gl.n - 1; g >= 0; g--) {
            if (gl.typ[g] == 0) {
                int P = gl.p1[g] + 1;
                int wi = gl.p2[g];
                int q = (lets >> (2 * wi)) & 3;
                int take = (path >> rbit) & 1;
                rbit++;
                if (q == 0 || q == P) {
                    if (take) coef = 0.0f;
                } else {
                    float th = rp[gl.p3[g]];
                    if (!take) {
                        coef *= cosf(th);
                    } else {
                        coef *= sinf(th);
                        int r = 6 - P - q;
                        int qp = (P == 1) ? 3 : P - 1;
                        coef = (q == qp) ? coef : -coef;
                        lets = (lets & ~(3 << (2 * wi))) | (r << (2 * wi));
                    }
                }
            } else {
                int c = gl.p1[g], tt = gl.p2[g];
                int a = (lets >> (2 * c)) & 3;
                int bb = (lets >> (2 * tt)) & 3;
                int At = (a == 1 || a == 2) ? 1 : 0;
                int Bc2 = (bb == 2 || bb == 3) ? 3 : 0;
                int k = 0;
                int nc = pmul_h(a, Bc2, k);
                int nt = pmul_h(At, bb, k);
                if ((k & 3) == 2) coef = -coef;
                lets = (lets & ~((3 << (2 * c)) | (3 << (2 * tt))))
                     | (nc << (2 * c)) | (nt << (2 * tt));
            }
        }
        int m = -1;
        if (coef != 0.0f) {
            int e[4], ok = 1;
            for (int wi = 0; wi < 4; wi++) {
                int L = (lets >> (2 * wi)) & 3;
                if (L == 2) { ok = 0; break; }
                e[wi] = (L == 0) ? 0 : ((L == 3) ? 1 : 2);
            }
            if (ok) m = e[0] * 27 + e[1] * 9 + e[2] * 3 + e[3];
        }
        e_m[tx] = m;
        e_c[tx] = coef;
    }
    __syncthreads();

    if (tx < 4) {
        for (int k = 0; k < 16; k++) {
            int m = e_m[tx * 16 + k];
            if (m >= 0) tab[m][tx] += e_c[tx * 16 + k];
        }
    }
    __syncthreads();

    if (tx < 64) {
        int w = tx >> 4, j = tx & 15;
        float c = (j < fp.nt[w]) ? tab[fp.mono[w * 16 + j]][w] : 0.0f;
        uint32_t uu = __float_as_uint(c);
        sc[w][j] = (ull)uu | ((ull)uu << 32);
    }
    __syncthreads();

    // ---- per-unit body ----
    auto body = [&](int u, float4 g00, float4 g01, float4 g10, float4 g11) {
        const float PI = 3.14159265358979323846f;
        float s0, c0, s1, c1;
        ull C0, S0, C1, S1, C2, S2, C3, S3;
        __sincosf(PI * g00.x, &s0, &c0); __sincosf(PI * g00.z, &s1, &c1);
        C0 = pk2f(c0, c1); S0 = pk2f(s0, s1);
        __sincosf(PI * g11.x, &s0, &c0); __sincosf(PI * g11.z, &s1, &c1);
        C1 = pk2f(c0, c1); S1 = pk2f(s0, s1);
        __sincosf(PI * g01.y, &s0, &c0); __sincosf(PI * g01.w, &s1, &c1);
        C2 = pk2f(c0, c1); S2 = pk2f(s0, s1);
        __sincosf(PI * g10.y, &s0, &c0); __sincosf(PI * g10.w, &s1, &c1);
        C3 = pk2f(c0, c1); S3 = pk2f(s0, s1);

        ull acc0 = 0, acc1 = 0, acc2 = 0, acc3 = 0;

#define DO_T(W, J, NN, AA, BB, ACC) \
        if constexpr (J < NN) { \
            constexpr int ec_ = (int)(((J < 8) ? (AA >> (8 * J)) : (BB >> (8 * (J - 8)))) & 255ULL); \
            ACC = fma2_(prod_ec<ec_>(C0, S0, C1, S1, C2, S2, C3, S3), sc[W][J], ACC); \
        }
#define DO_W(W, NN, AA, BB, ACC) \
        DO_T(W, 0, NN, AA, BB, ACC)  DO_T(W, 1, NN, AA, BB, ACC)  DO_T(W, 2, NN, AA, BB, ACC)  DO_T(W, 3, NN, AA, BB, ACC) \
        DO_T(W, 4, NN, AA, BB, ACC)  DO_T(W, 5, NN, AA, BB, ACC)  DO_T(W, 6, NN, AA, BB, ACC)  DO_T(W, 7, NN, AA, BB, ACC) \
        DO_T(W, 8, NN, AA, BB, ACC)  DO_T(W, 9, NN, AA, BB, ACC)  DO_T(W, 10, NN, AA, BB, ACC) DO_T(W, 11, NN, AA, BB, ACC) \
        DO_T(W, 12, NN, AA, BB, ACC) DO_T(W, 13, NN, AA, BB, ACC) DO_T(W, 14, NN, AA, BB, ACC) DO_T(W, 15, NN, AA, BB, ACC)

        DO_W(0, N0, A0, B0, acc0)
        DO_W(1, N1, A1, B1, acc1)
        DO_W(2, N2, A2, B2, acc2)
        DO_W(3, N3, A3, B3, acc3)
#undef DO_W
#undef DO_T

        float a0l, a0h, a1l, a1h, a2l, a2h, a3l, a3h;
        upk2f(acc0, a0l, a0h); upk2f(acc1, a1l, a1h);
        upk2f(acc2, a2l, a2h); upk2f(acc3, a3l, a3h);
        out4[2 * u]     = make_float4(a0l, a1l, a2l, a3l);
        out4[2 * u + 1] = make_float4(a0h, a1h, a2h, a3h);
    };

    if (v0) body(u0, f00, f01, f10, f11);

    // overhang units (UPB-512 = 79) handled by high-tx threads for balance
    if (tx >= 512 - (UPB - 512)) {
        int u1 = ustart + (UPB - 512) + tx;   // tx=433 -> ustart+512 ... tx=511 -> ustart+590
        if (u1 < uend) {
            int r00 = ((u1 >> 14) << 16) + (((u1 >> 9) & 31) << 11) + (((u1 >> 4) & 31) << 5) + (u1 & 15);
            float4 h00 = x4[r00];
            float4 h01 = x4[r00 + 16];
            float4 h10 = x4[r00 + 1024];
            float4 h11 = x4[r00 + 1040];
            body(u1, h00, h01, h10, h11);
        }
    }
}

// ============================================================================
// DENSE FALLBACK (proven R8/R10 kernels)
// ============================================================================
__device__ float4 g_coef4[162];

__device__ __forceinline__ float2 cmulf(float2 a, float2 b) {
    return make_float2(a.x * b.x - a.y * b.y, a.x * b.y + a.y * b.x);
}
__device__ __forceinline__ float2 caddf(float2 a, float2 b) {
    return make_float2(a.x + b.x, a.y + b.y);
}
__device__ __forceinline__ float Bc(int jb, int kb, int e) {
    if (jb != kb) return (e == 2) ? 0.5f : 0.0f;
    if (e == 2) return 0.0f;
    if (e == 0) return 0.5f;
    return jb ? -0.5f : 0.5f;
}

__global__ void quanv_setup(const float* __restrict__ rp, Ops4 ops) {
    __shared__ float2 U[16][16];
    __shared__ float ReM[4][16][16];
    __shared__ float G[4][9][16];
    int tid = threadIdx.x;

    if (tid < 16) {
        int col = tid;
        for (int m = 0; m < 16; m++)
            U[m][col] = make_float2(m == col ? 1.0f : 0.0f, 0.0f);
        for (int o = 0; o < ops.n; o++) {
            if (ops.type[o] == 0) {
                float th = rp[ops.c[o]];
                float ch = cosf(0.5f * th), sh = sinf(0.5f * th);
                float2 R00, R01, R10, R11;
                int kind = ops.a[o];
                if (kind == 0) {
                    R00 = make_float2(ch, 0); R11 = R00;
                    R01 = make_float2(0, -sh); R10 = R01;
                } else if (kind == 1) {
                    R00 = make_float2(ch, 0); R11 = R00;
                    R01 = make_float2(-sh, 0); R10 = make_float2(sh, 0);
                } else {
                    R00 = make_float2(ch, -sh); R11 = make_float2(ch, sh);
                    R01 = make_float2(0, 0);    R10 = make_float2(0, 0);
                }
                int bit = 1 << (3 - ops.b[o]);
                for (int m = 0; m < 16; m++) {
                    if (!(m & bit)) {
                        float2 x0 = U[m][col], x1 = U[m | bit][col];
                        U[m][col]       = caddf(cmulf(R00, x0), cmulf(R01, x1));
                        U[m | bit][col] = caddf(cmulf(R10, x0), cmulf(R11, x1));
                    }
                }
            } else {
                int cb = 1 << (3 - ops.a[o]);
                int tb = 1 << (3 - ops.b[o]);
                for (int m = 0; m < 16; m++) {
                    if ((m & cb) && !(m & tb)) {
                        float2 tmp = U[m][col];
                        U[m][col] = U[m | tb][col];
                        U[m | tb][col] = tmp;
                    }
                }
            }
        }
    }
    __syncthreads();

    for (int e = tid; e < 1024; e += blockDim.x) {
        int w = e >> 8, jk = e & 255, jj = jk >> 4, kk = jk & 15;
        int sbit = 1 << (3 - w);
        float sum = 0.0f;
        for (int m = 0; m < 16; m++) {
            float2 uj = U[m][jj], uk = U[m][kk];
            float re = uj.x * uk.x + uj.y * uk.y;
            sum += (m & sbit) ? -re : re;
        }
        ReM[w][jj][kk] = sum;
    }
    __syncthreads();

    for (int e = tid; e < 576; e += blockDim.x) {
        int w = e / 144, r = e % 144, p = r / 16, lk = r % 16;
        int jl = lk >> 2, kl = lk & 3;
        int e0 = p / 3, e1 = p % 3;
        float sum = 0.0f;
        for (int jh = 0; jh < 4; jh++)
            for (int kh = 0; kh < 4; kh++) {
                float w01 = Bc(jh >> 1, kh >> 1, e0) * Bc(jh & 1, kh & 1, e1);
                if (w01 != 0.0f)
                    sum += w01 * ReM[w][jh * 4 + jl][kh * 4 + kl];
            }
        G[w][p][lk] = sum;
    }
    __syncthreads();

    for (int m = tid; m < 81; m += blockDim.x) {
        int p = m / 9, q = m % 9;
        int e2 = q / 3, e3 = q % 3;
        float cw[4];
        for (int w = 0; w < 4; w++) {
            float sum = 0.0f;
            for (int jl = 0; jl < 4; jl++)
                for (int kl = 0; kl < 4; kl++) {
                    float w23 = Bc(jl >> 1, kl >> 1, e2) * Bc(jl & 1, kl & 1, e3);
                    if (w23 != 0.0f)
                        sum += w23 * G[w][p][jl * 4 + kl];
                }
            cw[w] = sum;
        }
        g_coef4[2 * m]     = make_float4(cw[0], cw[0], cw[1], cw[1]);
        g_coef4[2 * m + 1] = make_float4(cw[2], cw[2], cw[3], cw[3]);
    }
}

__global__ void __launch_bounds__(256) quanv_main(const float4* __restrict__ x4,
                                                  float4* __restrict__ out4) {
    __shared__ ulonglong2 shc[162];
    if (threadIdx.x < 162) {
        const ulonglong2* gc = reinterpret_cast<const ulonglong2*>(g_coef4);
        shc[threadIdx.x] = gc[threadIdx.x];
    }
    __syncthreads();

    int tid = blockIdx.x * 256 + threadIdx.x;
    int r00 = ((tid >> 14) << 16) + (((tid >> 9) & 31) << 11) + (((tid >> 4) & 31) << 5) + (tid & 15);
    float4 f00 = __ldcs(&x4[r00]);
    float4 f01 = __ldcs(&x4[r00 + 16]);
    float4 f10 = __ldcs(&x4[r00 + 1024]);
    float4 f11 = __ldcs(&x4[r00 + 1040]);

    const float PI = 3.14159265358979323846f;
    float s0, c0, s1, c1;
    ull C0, S0, C1, S1, C2, S2, C3, S3;
    __sincosf(PI * f00.x, &s0, &c0); __sincosf(PI * f00.z, &s1, &c1);
    C0 = pk2f(c0, c1); S0 = pk2f(s0, s1);
    __sincosf(PI * f11.x, &s0, &c0); __sincosf(PI * f11.z, &s1, &c1);
    C1 = pk2f(c0, c1); S1 = pk2f(s0, s1);
    __sincosf(PI * f01.y, &s0, &c0); __sincosf(PI * f01.w, &s1, &c1);
    C2 = pk2f(c0, c1); S2 = pk2f(s0, s1);
    __sincosf(PI * f10.y, &s0, &c0); __sincosf(PI * f10.w, &s1, &c1);
    C3 = pk2f(c0, c1); S3 = pk2f(s0, s1);

    ull v01[9], v23[9];
    v01[0] = 0; v23[0] = 0;
    v01[1] = C1; v01[2] = S1; v01[3] = C0;
    v01[4] = mul2_(C0, C1); v01[5] = mul2_(C0, S1);
    v01[6] = S0; v01[7] = mul2_(S0, C1); v01[8] = mul2_(S0, S1);
    v23[1] = C3; v23[2] = S3; v23[3] = C2;
    v23[4] = mul2_(C2, C3); v23[5] = mul2_(C2, S3);
    v23[6] = S2; v23[7] = mul2_(S2, C3); v23[8] = mul2_(S2, S3);

    ull acc0 = 0, acc1 = 0, acc2 = 0, acc3 = 0;

#pragma unroll
    for (int p = 0; p < 9; p++) {
#pragma unroll
        for (int q = 0; q < 9; q++) {
            int m = p * 9 + q;
            ulonglong2 ca = shc[2 * m];
            ulonglong2 cb = shc[2 * m + 1];
            if (p == 0 && q == 0) {
                acc0 = add2_(acc0, ca.x);
                acc1 = add2_(acc1, ca.y);
                acc2 = add2_(acc2, cb.x);
                acc3 = add2_(acc3, cb.y);
            } else {
                ull tpq = (p == 0) ? v23[q] : ((q == 0) ? v01[p] : mul2_(v01[p], v23[q]));
                acc0 = fma2_(tpq, ca.x, acc0);
                acc1 = fma2_(tpq, ca.y, acc1);
                acc2 = fma2_(tpq, cb.x, acc2);
                acc3 = fma2_(tpq, cb.y, acc3);
            }
        }
    }

    float a0l, a0h, a1l, a1h, a2l, a2h, a3l, a3h;
    upk2f(acc0, a0l, a0h); upk2f(acc1, a1l, a1h);
    upk2f(acc2, a2l, a2h); upk2f(acc3, a3l, a3h);
    out4[2 * tid]     = make_float4(a0l, a1l, a2l, a3l);
    out4[2 * tid + 1] = make_float4(a0h, a1h, a2h, a3h);
}

// ============================================================================
// Launch
// ============================================================================
static bool terms_equal(const TermsCx& a, const TermsCx& b) {
    for (int w = 0; w < 4; w++) {
        if (a.n[w] != b.n[w]) return false;
        for (int j = 0; j < a.n[w]; j++)
            if (a.ec[w][j] != b.ec[w][j] || a.mono[w][j] != b.mono[w][j]) return false;
    }
    return true;
}

extern "C" void kernel_launch(void* const* d_in, const int* in_sizes, int n_in,
                              void* d_out, int out_size) {
    const float* x  = (const float*)d_in[0];
    const float* rp = (const float*)d_in[1];
    if (n_in >= 2 && in_sizes[0] == 4) {
        const float* tmp = x; x = rp; rp = tmp;
    }

    int rv = find_variant_cx();     // runtime evaluation of same constexpr code
    if (rv < 0) {
        fputs("DIAG rng verification failed\n", stderr);
        fflush(stderr);
        return;
    }
    Ops4 rops = build_ops_cx(rv);
    TermsCx rt_ = derive_terms_cx(rops);

    bool cx_ok = (CXV >= 0) && (rv == CXV) && terms_equal(rt_, CXT) && rops.n <= 24;

    if (cx_ok) {
        GateListP gl;
        gl.n = rops.n;
        for (int o = 0; o < rops.n; o++) {
            gl.typ[o] = rops.type[o];
            gl.p1[o] = rops.a[o];
            gl.p2[o] = rops.b[o];
            gl.p3[o] = rops.c[o];
        }
        for (int o = rops.n; o < 24; o++) { gl.typ[o] = 0; gl.p1[o] = 0; gl.p2[o] = 0; gl.p3[o] = 0; }
        FillParam fp;
        for (int w = 0; w < 4; w++) {
            fp.nt[w] = rt_.n[w];
            for (int j = 0; j < 16; j++)
                fp.mono[w * 16 + j] = (j < rt_.n[w]) ? rt_.mono[w][j] : 0;
        }
        quanv_cx<CN0, CN1, CN2, CN3, CA0, CB0, CA1, CB1, CA2, CB2, CA3, CB3>
            <<<NBLK, 512>>>(rp, (const float4*)x, (float4*)d_out, gl, fp);
    } else {
        quanv_setup<<<1, 512>>>(rp, rops);
        quanv_main<<<1024, 256>>>((const float4*)x, (float4*)d_out);
    }
}

// round 13
// speedup vs baseline: 1.4627x; 1.0404x over previous
#include <cuda_runtime.h>
#include <cstdint>
#include <cstring>
#include <cstdio>

// ============================================================================
// Portable 128-bit (constexpr-safe, no __int128)
// ============================================================================
struct U128 { uint64_t hi, lo; };

constexpr U128 u128_mul64(uint64_t a, uint64_t b) {
    uint64_t a0 = a & 0xffffffffULL, a1 = a >> 32;
    uint64_t b0 = b & 0xffffffffULL, b1 = b >> 32;
    uint64_t p00 = a0 * b0, p01 = a0 * b1, p10 = a1 * b0, p11 = a1 * b1;
    uint64_t mid = (p00 >> 32) + (p01 & 0xffffffffULL) + (p10 & 0xffffffffULL);
    uint64_t lo = (p00 & 0xffffffffULL) | (mid << 32);
    uint64_t hi = p11 + (p01 >> 32) + (p10 >> 32) + (mid >> 32);
    return {hi, lo};
}
constexpr U128 u128_mul(U128 a, U128 b) {
    U128 ll = u128_mul64(a.lo, b.lo);
    return {ll.hi + a.lo * b.hi + a.hi * b.lo, ll.lo};
}
constexpr U128 u128_add(U128 a, U128 b) {
    uint64_t lo = a.lo + b.lo;
    return {a.hi + b.hi + (lo < a.lo ? 1u : 0u), lo};
}
constexpr U128 parse_dec128(const char* s) {
    U128 v{0, 0};
    for (; *s; s++) {
        v = u128_mul(v, U128{0, 10});
        v = u128_add(v, U128{0, (uint64_t)(*s - '0')});
    }
    return v;
}

// ============================================================================
// np.random.default_rng(42): direct raw PCG64 state (HW-verified R8-R12).
// ============================================================================
struct PcgCx {
    U128 state{0, 0}, inc{0, 0};
    int alg = 0, out_mode = 0;
    int has32 = 0;
    uint32_t buf32 = 0;

    constexpr void stepv() {
        if (alg == 0)
            state = u128_add(u128_mul(state, U128{0x2360ed051fc65da4ULL, 0x4385df649fccf645ULL}), inc);
        else
            state = u128_add(u128_mul(state, U128{0, 0xda942042e4dd58b5ULL}), inc);
    }
    constexpr uint64_t out_xslrr() const {
        uint64_t x = state.hi ^ state.lo;
        unsigned rot = (unsigned)(state.hi >> 58);
        return (x >> rot) | (x << ((64u - rot) & 63u));
    }
    constexpr uint64_t out_dxsm() const {
        uint64_t hi = state.hi, lo = state.lo | 1ULL;
        hi ^= hi >> 32; hi *= 0xda942042e4dd58b5ULL;
        hi ^= hi >> 48; hi *= lo;
        return hi;
    }
    constexpr uint64_t next64() {
        if (out_mode == 0) { stepv(); return alg == 0 ? out_xslrr() : out_dxsm(); }
        uint64_t r = alg == 0 ? out_xslrr() : out_dxsm();
        stepv();
        return r;
    }
    constexpr uint32_t next32() {
        if (has32) { has32 = 0; return buf32; }
        uint64_t n = next64();
        has32 = 1;
        buf32 = (uint32_t)(n >> 32);
        return (uint32_t)(n & 0xffffffffu);
    }
    constexpr double next_double() {
        return (double)(next64() >> 11) * (1.0 / 9007199254740992.0);
    }
    constexpr uint32_t lemire32(uint32_t rng) {
        uint32_t rng_excl = rng + 1u;
        uint64_t m = (uint64_t)next32() * (uint64_t)rng_excl;
        uint32_t leftover = (uint32_t)m;
        if (leftover < rng_excl) {
            uint32_t threshold = (uint32_t)((0xFFFFFFFFu - rng) % rng_excl);
            while (leftover < threshold) {
                m = (uint64_t)next32() * (uint64_t)rng_excl;
                leftover = (uint32_t)m;
            }
        }
        return (uint32_t)(m >> 32);
    }
    constexpr uint64_t random_interval(uint64_t mx) {
        if (mx == 0) return 0;
        uint64_t mask = mx;
        mask |= mask >> 1;  mask |= mask >> 2;  mask |= mask >> 4;
        mask |= mask >> 8;  mask |= mask >> 16; mask |= mask >> 32;
        uint64_t value = 0;
        while ((value = ((uint64_t)next32() & mask)) > mx) {}
        return value;
    }
};

constexpr void seed_direct_cx(PcgCx& r, int alg, int om) {
    r.alg = alg;
    r.out_mode = om;
    r.state = parse_dec128("274674114334540486603088602300644985544");
    r.inc   = parse_dec128("332724090758049132448979897138935081983");
    r.has32 = 0;
    r.buf32 = 0;
}
constexpr double dabs_cx(double x) { return x < 0 ? -x : x; }

constexpr int find_variant_cx() {
    for (int a = 0; a < 2; a++)
        for (int m = 0; m < 2; m++) {
            PcgCx r;
            seed_direct_cx(r, a, m);
            double d0 = r.next_double();
            double d1 = r.next_double();
            if (dabs_cx(d0 - 0.7739560485559633) < 1e-9 &&
                dabs_cx(d1 - 0.4388784397520523) < 1e-9)
                return a * 2 + m;
        }
    return -1;
}

#define MAXOPS 64
struct Ops4 {
    int n = 0;
    int type[MAXOPS] = {};
    int a[MAXOPS] = {};
    int b[MAXOPS] = {};
    int c[MAXOPS] = {};
};

constexpr Ops4 build_ops_cx(int variant) {
    Ops4 ops{};
    PcgCx rng;
    seed_direct_cx(rng, variant >> 1, variant & 1);
    int i = 0;
    while (i < 4 && ops.n < MAXOPS) {
        if (rng.next_double() > 0.3) {
            int kind = (int)rng.lemire32(2);
            int w    = (int)rng.lemire32(3);
            ops.type[ops.n] = 0; ops.a[ops.n] = kind; ops.b[ops.n] = w; ops.c[ops.n] = i;
            ops.n++; i++;
        } else {
            int arr[4] = {0, 1, 2, 3};
            for (int t = 3; t >= 1; t--) {
                int j = (int)rng.random_interval((uint64_t)t);
                int tmp = arr[t]; arr[t] = arr[j]; arr[j] = tmp;
            }
            ops.type[ops.n] = 1; ops.a[ops.n] = arr[0]; ops.b[ops.n] = arr[1]; ops.c[ops.n] = 0;
            ops.n++;
        }
    }
    return ops;
}

// Pauli product (0=I,1=X,2=Y,3=Z): sigma_a*sigma_b = i^k sigma_r
__host__ __device__ constexpr int pmul_h(int a, int b, int& k) {
    if (a == 0) return b;
    if (b == 0) return a;
    if (a == b) return 0;
    int r = 6 - a - b;
    k += (b == (a % 3) + 1) ? 1 : 3;
    return r;
}

// Structural term derivation + path->term map + trig-usage flags
struct TermsCx {
    int n[4] = {};
    int ec[4][16] = {};    // e-code: e0|e1<<2|e2<<4|e3<<6, e: 0=I,1=C,2=S
    int pt[4][16] = {};    // path -> term index, -1 if none
    bool uc[4] = {}, us[4] = {};
};

constexpr TermsCx derive_terms_cx(const Ops4& ops) {
    TermsCx t{};
    for (int w = 0; w < 4; w++)
        for (int p = 0; p < 16; p++) t.pt[w][p] = -1;
    for (int w = 0; w < 4; w++) {
        for (int path = 0; path < 16; path++) {
            int lets = 3 << (2 * w);
            bool dead = false;
            int rbit = 0;
            for (int g = ops.n - 1; g >= 0 && !dead; g--) {
                if (ops.type[g] == 0) {
                    int P = ops.a[g] + 1;
                    int wi = ops.b[g];
                    int q = (lets >> (2 * wi)) & 3;
                    int take = (path >> rbit) & 1;
                    rbit++;
                    if (q == 0 || q == P) {
                        if (take) dead = true;
                    } else if (take) {
                        int r = 6 - P - q;
                        lets = (lets & ~(3 << (2 * wi))) | (r << (2 * wi));
                    }
                } else {
                    int c = ops.a[g], tt = ops.b[g];
                    int a = (lets >> (2 * c)) & 3;
                    int bb = (lets >> (2 * tt)) & 3;
                    int At = (a == 1 || a == 2) ? 1 : 0;
                    int Bc2 = (bb == 2 || bb == 3) ? 3 : 0;
                    int k = 0;
                    int nc = pmul_h(a, Bc2, k);
                    int nt = pmul_h(At, bb, k);
                    lets = (lets & ~((3 << (2 * c)) | (3 << (2 * tt))))
                         | (nc << (2 * c)) | (nt << (2 * tt));
                }
            }
            if (dead) continue;
            int e[4] = {}, ok = 1;
            for (int wi = 0; wi < 4; wi++) {
                int L = (lets >> (2 * wi)) & 3;
                if (L == 2) { ok = 0; break; }
                e[wi] = (L == 0) ? 0 : ((L == 3) ? 1 : 2);
            }
            if (!ok) continue;
            int ecb = e[0] | (e[1] << 2) | (e[2] << 4) | (e[3] << 6);
            int idx = -1;
            for (int jj = 0; jj < t.n[w]; jj++)
                if (t.ec[w][jj] == ecb) { idx = jj; break; }
            if (idx < 0 && t.n[w] < 16) {
                idx = t.n[w];
                t.ec[w][idx] = ecb;
                t.n[w]++;
            }
            t.pt[w][path] = idx;
        }
    }
    for (int w = 0; w < 4; w++)
        for (int jj = 0; jj < t.n[w]; jj++)
            for (int wi = 0; wi < 4; wi++) {
                int e = (t.ec[w][jj] >> (2 * wi)) & 3;
                if (e == 1) t.uc[wi] = true;
                if (e == 2) t.us[wi] = true;
            }
    return t;
}

constexpr uint64_t pack_ec8(const TermsCx& t, int w, int lohalf) {
    uint64_t v = 0;
    for (int j = 0; j < 8; j++) {
        int jj = lohalf * 8 + j;
        if (jj < t.n[w]) v |= ((uint64_t)(t.ec[w][jj] & 0xff)) << (8 * j);
    }
    return v;
}
constexpr uint64_t pack_pt(const TermsCx& t, int w) {
    uint64_t v = 0;
    for (int p = 0; p < 16; p++) {
        uint64_t q = (t.pt[w][p] < 0) ? 15ULL : (uint64_t)t.pt[w][p];
        v |= q << (4 * p);
    }
    return v;
}
constexpr int pack_ucs(const TermsCx& t) {
    int v = 0;
    for (int w = 0; w < 4; w++) {
        if (t.uc[w]) v |= 1 << w;
        if (t.us[w]) v |= 1 << (4 + w);
    }
    return v;
}

// ---- compile-time constants ----
constexpr int     CXV   = find_variant_cx();
constexpr Ops4    CXOPS = build_ops_cx(CXV < 0 ? 0 : CXV);
constexpr TermsCx CXT   = (CXV >= 0) ? derive_terms_cx(CXOPS) : TermsCx{};
constexpr int CN0 = CXT.n[0], CN1 = CXT.n[1], CN2 = CXT.n[2], CN3 = CXT.n[3];
constexpr uint64_t CA0 = pack_ec8(CXT, 0, 0), CB0 = pack_ec8(CXT, 0, 1);
constexpr uint64_t CA1 = pack_ec8(CXT, 1, 0), CB1 = pack_ec8(CXT, 1, 1);
constexpr uint64_t CA2 = pack_ec8(CXT, 2, 0), CB2 = pack_ec8(CXT, 2, 1);
constexpr uint64_t CA3 = pack_ec8(CXT, 3, 0), CB3 = pack_ec8(CXT, 3, 1);
constexpr uint64_t CP0 = pack_pt(CXT, 0), CP1 = pack_pt(CXT, 1);
constexpr uint64_t CP2 = pack_pt(CXT, 2), CP3 = pack_pt(CXT, 3);
constexpr int CUCS = pack_ucs(CXT);

// ============================================================================
// Device helpers
// ============================================================================
typedef unsigned long long ull;

__device__ __forceinline__ ull pk2f(float lo, float hi) {
    ull r; asm("mov.b64 %0, {%1, %2};" : "=l"(r) : "f"(lo), "f"(hi)); return r;
}
__device__ __forceinline__ void upk2f(ull v, float& lo, float& hi) {
    asm("mov.b64 {%0, %1}, %2;" : "=f"(lo), "=f"(hi) : "l"(v));
}
__device__ __forceinline__ ull fma2_(ull a, ull b, ull c) {
    ull d; asm("fma.rn.f32x2 %0, %1, %2, %3;" : "=l"(d) : "l"(a), "l"(b), "l"(c)); return d;
}
__device__ __forceinline__ ull mul2_(ull a, ull b) {
    ull d; asm("mul.rn.f32x2 %0, %1, %2;" : "=l"(d) : "l"(a), "l"(b)); return d;
}
__device__ __forceinline__ ull add2_(ull a, ull b) {
    ull d; asm("add.rn.f32x2 %0, %1, %2;" : "=l"(d) : "l"(a), "l"(b)); return d;
}

template <int EC>
__device__ __forceinline__ ull prod_ec(ull C0, ull S0, ull C1, ull S1,
                                       ull C2, ull S2, ull C3, ull S3) {
    constexpr int e0 = EC & 3, e1 = (EC >> 2) & 3, e2 = (EC >> 4) & 3, e3 = (EC >> 6) & 3;
    ull u = 0x3f8000003f800000ULL;
    if constexpr (e0 == 1) u = C0; else if constexpr (e0 == 2) u = S0;
    constexpr bool h0 = (e0 != 0);
    if constexpr (e1 != 0) { ull f = (e1 == 1) ? C1 : S1; if constexpr (h0) u = mul2_(u, f); else u = f; }
    constexpr bool h1 = h0 || (e1 != 0);
    if constexpr (e2 != 0) { ull f = (e2 == 1) ? C2 : S2; if constexpr (h1) u = mul2_(u, f); else u = f; }
    constexpr bool h2 = h1 || (e2 != 0);
    if constexpr (e3 != 0) { ull f = (e3 == 1) ? C3 : S3; if constexpr (h2) u = mul2_(u, f); else u = f; }
    return u;
}

// ============================================================================
// FUSED KERNEL (compile-time term structure + path maps + trig gating)
// ============================================================================
struct GateListP {
    int n;
    int typ[24];
    int p1[24];
    int p2[24];
    int p3[24];
};

#define NBLK 444
#define UPB  591   // 444*591 = 262404 >= 262144 units

template <int N0, int N1, int N2, int N3,
          ull A0, ull B0, ull A1, ull B1, ull A2, ull B2, ull A3, ull B3,
          ull P0, ull P1, ull P2, ull P3, int UCS>
__global__ void __launch_bounds__(512, 3) quanv_cx(const float* __restrict__ rp,
                                                   const float4* __restrict__ x4,
                                                   float4* __restrict__ out4,
                                                   GateListP gl) {
    __shared__ float e_c[64];

    const int tx = threadIdx.x;
    const int ustart = blockIdx.x * UPB;
    const int uend   = min(ustart + UPB, 262144);
    const int u0 = ustart + tx;
    const bool v0 = (u0 < uend);

    // ---- early loads for unit 0 ----
    float4 f00, f01, f10, f11;
    if (v0) {
        int r00 = ((u0 >> 14) << 16) + (((u0 >> 9) & 31) << 11) + (((u0 >> 4) & 31) << 5) + (u0 & 15);
        f00 = x4[r00];
        f01 = x4[r00 + 16];
        f10 = x4[r00 + 1024];
        f11 = x4[r00 + 1040];
    }

    // ---- Pauli back-propagation: 4 wires x 16 paths ----
    if (tx < 64) {
        int w = tx >> 4, path = tx & 15;
        int lets = 3 << (2 * w);
        float coef = 1.0f;
        int rbit = 0;
        for (int g = gl.n - 1; g >= 0; g--) {
            if (gl.typ[g] == 0) {
                int P = gl.p1[g] + 1;
                int wi = gl.p2[g];
                int q = (lets >> (2 * wi)) & 3;
                int take = (path >> rbit) & 1;
                rbit++;
                if (q == 0 || q == P) {
                    if (take) coef = 0.0f;
                } else {
                    float th = rp[gl.p3[g]];
                    if (!take) {
                        coef *= cosf(th);
                    } else {
                        coef *= sinf(th);
                        int r = 6 - P - q;
                        int qp = (P == 1) ? 3 : P - 1;
                        coef = (q == qp) ? coef : -coef;
                        lets = (lets & ~(3 << (2 * wi))) | (r << (2 * wi));
                    }
                }
            } else {
                int c = gl.p1[g], tt = gl.p2[g];
                int a = (lets >> (2 * c)) & 3;
                int bb = (lets >> (2 * tt)) & 3;
                int At = (a == 1 || a == 2) ? 1 : 0;
                int Bc2 = (bb == 2 || bb == 3) ? 3 : 0;
                int k = 0;
                int nc = pmul_h(a, Bc2, k);
                int nt = pmul_h(At, bb, k);
                if ((k & 3) == 2) coef = -coef;
                lets = (lets & ~((3 << (2 * c)) | (3 << (2 * tt))))
                     | (nc << (2 * c)) | (nt << (2 * tt));
            }
        }
        e_c[tx] = coef;
    }
    __syncthreads();   // the ONLY barrier

    // ---- fold paths -> per-term duplicated-pair coefficients (registers) ----
    ull cw0[N0 > 0 ? N0 : 1], cw1[N1 > 0 ? N1 : 1], cw2[N2 > 0 ? N2 : 1], cw3[N3 > 0 ? N3 : 1];
#define FOLD_W(W, NN, PP, ARR) \
    _Pragma("unroll") \
    for (int j = 0; j < NN; j++) { \
        float s_ = 0.0f; \
        _Pragma("unroll") \
        for (int p = 0; p < 16; p++) \
            if (((PP >> (4 * p)) & 15ULL) == (ull)j) s_ += e_c[W * 16 + p]; \
        uint32_t uu_ = __float_as_uint(s_); \
        ARR[j] = (ull)uu_ | ((ull)uu_ << 32); \
    }
    FOLD_W(0, N0, P0, cw0)
    FOLD_W(1, N1, P1, cw1)
    FOLD_W(2, N2, P2, cw2)
    FOLD_W(3, N3, P3, cw3)
#undef FOLD_W

    constexpr bool uc0 = UCS & 1, uc1 = UCS & 2, uc2 = UCS & 4, uc3 = UCS & 8;
    constexpr bool us0 = UCS & 16, us1 = UCS & 32, us2 = UCS & 64, us3 = UCS & 128;

    // ---- per-unit body ----
    auto body = [&](int u, float4 g00, float4 g01, float4 g10, float4 g11) {
        const float PI = 3.14159265358979323846f;
        ull C0 = 0, S0 = 0, C1 = 0, S1 = 0, C2 = 0, S2 = 0, C3 = 0, S3 = 0;
        float sa, ca, sb, cb;

#define TRIG_W(UC, US, XLO, XHI, CV, SV) \
        if constexpr (UC && US) { \
            __sincosf(PI * (XLO), &sa, &ca); __sincosf(PI * (XHI), &sb, &cb); \
            CV = pk2f(ca, cb); SV = pk2f(sa, sb); \
        } else if constexpr (UC) { \
            CV = pk2f(__cosf(PI * (XLO)), __cosf(PI * (XHI))); \
        } else if constexpr (US) { \
            SV = pk2f(__sinf(PI * (XLO)), __sinf(PI * (XHI))); \
        }
        TRIG_W(uc0, us0, g00.x, g00.z, C0, S0)
        TRIG_W(uc1, us1, g11.x, g11.z, C1, S1)
        TRIG_W(uc2, us2, g01.y, g01.w, C2, S2)
        TRIG_W(uc3, us3, g10.y, g10.w, C3, S3)
#undef TRIG_W

        ull acc0 = 0, acc1 = 0, acc2 = 0, acc3 = 0;

#define DO_T(W, J, NN, AA, BB, ACC, ARR) \
        if constexpr (J < NN) { \
            constexpr int ec_ = (int)(((J < 8) ? (AA >> (8 * J)) : (BB >> (8 * (J - 8)))) & 255ULL); \
            ACC = fma2_(prod_ec<ec_>(C0, S0, C1, S1, C2, S2, C3, S3), ARR[J], ACC); \
        }
#define DO_W(W, NN, AA, BB, ACC, ARR) \
        DO_T(W, 0, NN, AA, BB, ACC, ARR)  DO_T(W, 1, NN, AA, BB, ACC, ARR)  DO_T(W, 2, NN, AA, BB, ACC, ARR)  DO_T(W, 3, NN, AA, BB, ACC, ARR) \
        DO_T(W, 4, NN, AA, BB, ACC, ARR)  DO_T(W, 5, NN, AA, BB, ACC, ARR)  DO_T(W, 6, NN, AA, BB, ACC, ARR)  DO_T(W, 7, NN, AA, BB, ACC, ARR) \
        DO_T(W, 8, NN, AA, BB, ACC, ARR)  DO_T(W, 9, NN, AA, BB, ACC, ARR)  DO_T(W, 10, NN, AA, BB, ACC, ARR) DO_T(W, 11, NN, AA, BB, ACC, ARR) \
        DO_T(W, 12, NN, AA, BB, ACC, ARR) DO_T(W, 13, NN, AA, BB, ACC, ARR) DO_T(W, 14, NN, AA, BB, ACC, ARR) DO_T(W, 15, NN, AA, BB, ACC, ARR)

        DO_W(0, N0, A0, B0, acc0, cw0)
        DO_W(1, N1, A1, B1, acc1, cw1)
        DO_W(2, N2, A2, B2, acc2, cw2)
        DO_W(3, N3, A3, B3, acc3, cw3)
#undef DO_W
#undef DO_T

        float a0l, a0h, a1l, a1h, a2l, a2h, a3l, a3h;
        upk2f(acc0, a0l, a0h); upk2f(acc1, a1l, a1h);
        upk2f(acc2, a2l, a2h); upk2f(acc3, a3l, a3h);
        __stcs(&out4[2 * u],     make_float4(a0l, a1l, a2l, a3l));
        __stcs(&out4[2 * u + 1], make_float4(a0h, a1h, a2h, a3h));
    };

    if (v0) body(u0, f00, f01, f10, f11);

    // overhang units (UPB-512 = 79) on high-tx threads
    if (tx >= 512 - (UPB - 512)) {
        int u1 = ustart + (UPB - 512) + tx;
        if (u1 < uend) {
            int r00 = ((u1 >> 14) << 16) + (((u1 >> 9) & 31) << 11) + (((u1 >> 4) & 31) << 5) + (u1 & 15);
            float4 h00 = x4[r00];
            float4 h01 = x4[r00 + 16];
            float4 h10 = x4[r00 + 1024];
            float4 h11 = x4[r00 + 1040];
            body(u1, h00, h01, h10, h11);
        }
    }
}

// ============================================================================
// DENSE FALLBACK (proven R8 kernels)
// ============================================================================
__device__ float4 g_coef4[162];

__device__ __forceinline__ float2 cmulf(float2 a, float2 b) {
    return make_float2(a.x * b.x - a.y * b.y, a.x * b.y + a.y * b.x);
}
__device__ __forceinline__ float2 caddf(float2 a, float2 b) {
    return make_float2(a.x + b.x, a.y + b.y);
}
__device__ __forceinline__ float Bc(int jb, int kb, int e) {
    if (jb != kb) return (e == 2) ? 0.5f : 0.0f;
    if (e == 2) return 0.0f;
    if (e == 0) return 0.5f;
    return jb ? -0.5f : 0.5f;
}

__global__ void quanv_setup(const float* __restrict__ rp, Ops4 ops) {
    __shared__ float2 U[16][16];
    __shared__ float ReM[4][16][16];
    __shared__ float G[4][9][16];
    int tid = threadIdx.x;

    if (tid < 16) {
        int col = tid;
        for (int m = 0; m < 16; m++)
            U[m][col] = make_float2(m == col ? 1.0f : 0.0f, 0.0f);
        for (int o = 0; o < ops.n; o++) {
            if (ops.type[o] == 0) {
                float th = rp[ops.c[o]];
                float ch = cosf(0.5f * th), sh = sinf(0.5f * th);
                float2 R00, R01, R10, R11;
                int kind = ops.a[o];
                if (kind == 0) {
                    R00 = make_float2(ch, 0); R11 = R00;
                    R01 = make_float2(0, -sh); R10 = R01;
                } else if (kind == 1) {
                    R00 = make_float2(ch, 0); R11 = R00;
                    R01 = make_float2(-sh, 0); R10 = make_float2(sh, 0);
                } else {
                    R00 = make_float2(ch, -sh); R11 = make_float2(ch, sh);
                    R01 = make_float2(0, 0);    R10 = make_float2(0, 0);
                }
                int bit = 1 << (3 - ops.b[o]);
                for (int m = 0; m < 16; m++) {
                    if (!(m & bit)) {
                        float2 x0 = U[m][col], x1 = U[m | bit][col];
                        U[m][col]       = caddf(cmulf(R00, x0), cmulf(R01, x1));
                        U[m | bit][col] = caddf(cmulf(R10, x0), cmulf(R11, x1));
                    }
                }
            } else {
                int cb = 1 << (3 - ops.a[o]);
                int tb = 1 << (3 - ops.b[o]);
                for (int m = 0; m < 16; m++) {
                    if ((m & cb) && !(m & tb)) {
                        float2 tmp = U[m][col];
                        U[m][col] = U[m | tb][col];
                        U[m | tb][col] = tmp;
                    }
                }
            }
        }
    }
    __syncthreads();

    for (int e = tid; e < 1024; e += blockDim.x) {
        int w = e >> 8, jk = e & 255, jj = jk >> 4, kk = jk & 15;
        int sbit = 1 << (3 - w);
        float sum = 0.0f;
        for (int m = 0; m < 16; m++) {
            float2 uj = U[m][jj], uk = U[m][kk];
            float re = uj.x * uk.x + uj.y * uk.y;
            sum += (m & sbit) ? -re : re;
        }
        ReM[w][jj][kk] = sum;
    }
    __syncthreads();

    for (int e = tid; e < 576; e += blockDim.x) {
        int w = e / 144, r = e % 144, p = r / 16, lk = r % 16;
        int jl = lk >> 2, kl = lk & 3;
        int e0 = p / 3, e1 = p % 3;
        float sum = 0.0f;
        for (int jh = 0; jh < 4; jh++)
            for (int kh = 0; kh < 4; kh++) {
                float w01 = Bc(jh >> 1, kh >> 1, e0) * Bc(jh & 1, kh & 1, e1);
                if (w01 != 0.0f)
                    sum += w01 * ReM[w][jh * 4 + jl][kh * 4 + kl];
            }
        G[w][p][lk] = sum;
    }
    __syncthreads();

    for (int m = tid; m < 81; m += blockDim.x) {
        int p = m / 9, q = m % 9;
        int e2 = q / 3, e3 = q % 3;
        float cw[4];
        for (int w = 0; w < 4; w++) {
            float sum = 0.0f;
            for (int jl = 0; jl < 4; jl++)
                for (int kl = 0; kl < 4; kl++) {
                    float w23 = Bc(jl >> 1, kl >> 1, e2) * Bc(jl & 1, kl & 1, e3);
                    if (w23 != 0.0f)
                        sum += w23 * G[w][p][jl * 4 + kl];
                }
            cw[w] = sum;
        }
        g_coef4[2 * m]     = make_float4(cw[0], cw[0], cw[1], cw[1]);
        g_coef4[2 * m + 1] = make_float4(cw[2], cw[2], cw[3], cw[3]);
    }
}

__global__ void __launch_bounds__(256) quanv_main(const float4* __restrict__ x4,
                                                  float4* __restrict__ out4) {
    __shared__ ulonglong2 shc[162];
    if (threadIdx.x < 162) {
        const ulonglong2* gc = reinterpret_cast<const ulonglong2*>(g_coef4);
        shc[threadIdx.x] = gc[threadIdx.x];
    }
    __syncthreads();

    int tid = blockIdx.x * 256 + threadIdx.x;
    int r00 = ((tid >> 14) << 16) + (((tid >> 9) & 31) << 11) + (((tid >> 4) & 31) << 5) + (tid & 15);
    float4 f00 = __ldcs(&x4[r00]);
    float4 f01 = __ldcs(&x4[r00 + 16]);
    float4 f10 = __ldcs(&x4[r00 + 1024]);
    float4 f11 = __ldcs(&x4[r00 + 1040]);

    const float PI = 3.14159265358979323846f;
    float s0, c0, s1, c1;
    ull C0, S0, C1, S1, C2, S2, C3, S3;
    __sincosf(PI * f00.x, &s0, &c0); __sincosf(PI * f00.z, &s1, &c1);
    C0 = pk2f(c0, c1); S0 = pk2f(s0, s1);
    __sincosf(PI * f11.x, &s0, &c0); __sincosf(PI * f11.z, &s1, &c1);
    C1 = pk2f(c0, c1); S1 = pk2f(s0, s1);
    __sincosf(PI * f01.y, &s0, &c0); __sincosf(PI * f01.w, &s1, &c1);
    C2 = pk2f(c0, c1); S2 = pk2f(s0, s1);
    __sincosf(PI * f10.y, &s0, &c0); __sincosf(PI * f10.w, &s1, &c1);
    C3 = pk2f(c0, c1); S3 = pk2f(s0, s1);

    ull v01[9], v23[9];
    v01[0] = 0; v23[0] = 0;
    v01[1] = C1; v01[2] = S1; v01[3] = C0;
    v01[4] = mul2_(C0, C1); v01[5] = mul2_(C0, S1);
    v01[6] = S0; v01[7] = mul2_(S0, C1); v01[8] = mul2_(S0, S1);
    v23[1] = C3; v23[2] = S3; v23[3] = C2;
    v23[4] = mul2_(C2, C3); v23[5] = mul2_(C2, S3);
    v23[6] = S2; v23[7] = mul2_(S2, C3); v23[8] = mul2_(S2, S3);

    ull acc0 = 0, acc1 = 0, acc2 = 0, acc3 = 0;

#pragma unroll
    for (int p = 0; p < 9; p++) {
#pragma unroll
        for (int q = 0; q < 9; q++) {
            int m = p * 9 + q;
            ulonglong2 ca = shc[2 * m];
            ulonglong2 cb = shc[2 * m + 1];
            if (p == 0 && q == 0) {
                acc0 = add2_(acc0, ca.x);
                acc1 = add2_(acc1, ca.y);
                acc2 = add2_(acc2, cb.x);
                acc3 = add2_(acc3, cb.y);
            } else {
                ull tpq = (p == 0) ? v23[q] : ((q == 0) ? v01[p] : mul2_(v01[p], v23[q]));
                acc0 = fma2_(tpq, ca.x, acc0);
                acc1 = fma2_(tpq, ca.y, acc1);
                acc2 = fma2_(tpq, cb.x, acc2);
                acc3 = fma2_(tpq, cb.y, acc3);
            }
        }
    }

    float a0l, a0h, a1l, a1h, a2l, a2h, a3l, a3h;
    upk2f(acc0, a0l, a0h); upk2f(acc1, a1l, a1h);
    upk2f(acc2, a2l, a2h); upk2f(acc3, a3l, a3h);
    out4[2 * tid]     = make_float4(a0l, a1l, a2l, a3l);
    out4[2 * tid + 1] = make_float4(a0h, a1h, a2h, a3h);
}

// ============================================================================
// Launch
// ============================================================================
static bool terms_equal(const TermsCx& a, const TermsCx& b) {
    for (int w = 0; w < 4; w++) {
        if (a.n[w] != b.n[w]) return false;
        if (a.uc[w] != b.uc[w] || a.us[w] != b.us[w]) return false;
        for (int j = 0; j < a.n[w]; j++)
            if (a.ec[w][j] != b.ec[w][j]) return false;
        for (int p = 0; p < 16; p++)
            if (a.pt[w][p] != b.pt[w][p]) return false;
    }
    return true;
}

extern "C" void kernel_launch(void* const* d_in, const int* in_sizes, int n_in,
                              void* d_out, int out_size) {
    const float* x  = (const float*)d_in[0];
    const float* rp = (const float*)d_in[1];
    if (n_in >= 2 && in_sizes[0] == 4) {
        const float* tmp = x; x = rp; rp = tmp;
    }

    int rv = find_variant_cx();
    if (rv < 0) {
        fputs("DIAG rng verification failed\n", stderr);
        fflush(stderr);
        return;
    }
    Ops4 rops = build_ops_cx(rv);
    TermsCx rt_ = derive_terms_cx(rops);

    bool cx_ok = (CXV >= 0) && (rv == CXV) && terms_equal(rt_, CXT) && rops.n <= 24;

    if (cx_ok) {
        GateListP gl;
        gl.n = rops.n;
        for (int o = 0; o < rops.n; o++) {
            gl.typ[o] = rops.type[o];
            gl.p1[o] = rops.a[o];
            gl.p2[o] = rops.b[o];
            gl.p3[o] = rops.c[o];
        }
        for (int o = rops.n; o < 24; o++) { gl.typ[o] = 0; gl.p1[o] = 0; gl.p2[o] = 0; gl.p3[o] = 0; }
        quanv_cx<CN0, CN1, CN2, CN3, CA0, CB0, CA1, CB1, CA2, CB2, CA3, CB3,
                 CP0, CP1, CP2, CP3, CUCS>
            <<<NBLK, 512>>>(rp, (const float4*)x, (float4*)d_out, gl);
    } else {
        quanv_setup<<<1, 512>>>(rp, rops);
        quanv_main<<<1024, 256>>>((const float4*)x, (float4*)d_out);
    }
}

// round 15
// speedup vs baseline: 1.7444x; 1.1926x over previous
#include <cuda_runtime.h>
#include <cstdint>
#include <cstring>
#include <cstdio>

// ============================================================================
// Portable 128-bit (constexpr-safe, no __int128)
// ============================================================================
struct U128 { uint64_t hi, lo; };

__host__ __device__ constexpr U128 u128_mul64(uint64_t a, uint64_t b) {
    uint64_t a0 = a & 0xffffffffULL, a1 = a >> 32;
    uint64_t b0 = b & 0xffffffffULL, b1 = b >> 32;
    uint64_t p00 = a0 * b0, p01 = a0 * b1, p10 = a1 * b0, p11 = a1 * b1;
    uint64_t mid = (p00 >> 32) + (p01 & 0xffffffffULL) + (p10 & 0xffffffffULL);
    uint64_t lo = (p00 & 0xffffffffULL) | (mid << 32);
    uint64_t hi = p11 + (p01 >> 32) + (p10 >> 32) + (mid >> 32);
    return {hi, lo};
}
__host__ __device__ constexpr U128 u128_mul(U128 a, U128 b) {
    U128 ll = u128_mul64(a.lo, b.lo);
    return {ll.hi + a.lo * b.hi + a.hi * b.lo, ll.lo};
}
__host__ __device__ constexpr U128 u128_add(U128 a, U128 b) {
    uint64_t lo = a.lo + b.lo;
    return {a.hi + b.hi + (lo < a.lo ? 1u : 0u), lo};
}
__host__ __device__ constexpr U128 parse_dec128(const char* s) {
    U128 v{0, 0};
    for (; *s; s++) {
        v = u128_mul(v, U128{0, 10});
        v = u128_add(v, U128{0, (uint64_t)(*s - '0')});
    }
    return v;
}

// ============================================================================
// np.random.default_rng(42): direct raw PCG64 state (HW-verified R8-R13).
// ============================================================================
struct PcgCx {
    U128 state{0, 0}, inc{0, 0};
    int alg = 0, out_mode = 0;
    int has32 = 0;
    uint32_t buf32 = 0;

    __host__ __device__ constexpr void stepv() {
        if (alg == 0)
            state = u128_add(u128_mul(state, U128{0x2360ed051fc65da4ULL, 0x4385df649fccf645ULL}), inc);
        else
            state = u128_add(u128_mul(state, U128{0, 0xda942042e4dd58b5ULL}), inc);
    }
    __host__ __device__ constexpr uint64_t out_xslrr() const {
        uint64_t x = state.hi ^ state.lo;
        unsigned rot = (unsigned)(state.hi >> 58);
        return (x >> rot) | (x << ((64u - rot) & 63u));
    }
    __host__ __device__ constexpr uint64_t out_dxsm() const {
        uint64_t hi = state.hi, lo = state.lo | 1ULL;
        hi ^= hi >> 32; hi *= 0xda942042e4dd58b5ULL;
        hi ^= hi >> 48; hi *= lo;
        return hi;
    }
    __host__ __device__ constexpr uint64_t next64() {
        if (out_mode == 0) { stepv(); return alg == 0 ? out_xslrr() : out_dxsm(); }
        uint64_t r = alg == 0 ? out_xslrr() : out_dxsm();
        stepv();
        return r;
    }
    __host__ __device__ constexpr uint32_t next32() {
        if (has32) { has32 = 0; return buf32; }
        uint64_t n = next64();
        has32 = 1;
        buf32 = (uint32_t)(n >> 32);
        return (uint32_t)(n & 0xffffffffu);
    }
    __host__ __device__ constexpr double next_double() {
        return (double)(next64() >> 11) * (1.0 / 9007199254740992.0);
    }
    __host__ __device__ constexpr uint32_t lemire32(uint32_t rng) {
        uint32_t rng_excl = rng + 1u;
        uint64_t m = (uint64_t)next32() * (uint64_t)rng_excl;
        uint32_t leftover = (uint32_t)m;
        if (leftover < rng_excl) {
            uint32_t threshold = (uint32_t)((0xFFFFFFFFu - rng) % rng_excl);
            while (leftover < threshold) {
                m = (uint64_t)next32() * (uint64_t)rng_excl;
                leftover = (uint32_t)m;
            }
        }
        return (uint32_t)(m >> 32);
    }
    __host__ __device__ constexpr uint64_t random_interval(uint64_t mx) {
        if (mx == 0) return 0;
        uint64_t mask = mx;
        mask |= mask >> 1;  mask |= mask >> 2;  mask |= mask >> 4;
        mask |= mask >> 8;  mask |= mask >> 16; mask |= mask >> 32;
        uint64_t value = 0;
        while ((value = ((uint64_t)next32() & mask)) > mx) {}
        return value;
    }
};

__host__ __device__ constexpr void seed_direct_cx(PcgCx& r, int alg, int om) {
    r.alg = alg;
    r.out_mode = om;
    r.state = parse_dec128("274674114334540486603088602300644985544");
    r.inc   = parse_dec128("332724090758049132448979897138935081983");
    r.has32 = 0;
    r.buf32 = 0;
}
__host__ __device__ constexpr double dabs_cx(double x) { return x < 0 ? -x : x; }

__host__ __device__ constexpr int find_variant_cx() {
    for (int a = 0; a < 2; a++)
        for (int m = 0; m < 2; m++) {
            PcgCx r;
            seed_direct_cx(r, a, m);
            double d0 = r.next_double();
            double d1 = r.next_double();
            if (dabs_cx(d0 - 0.7739560485559633) < 1e-9 &&
                dabs_cx(d1 - 0.4388784397520523) < 1e-9)
                return a * 2 + m;
        }
    return -1;
}

#define MAXOPS 64
struct Ops4 {
    int n = 0;
    int type[MAXOPS] = {};
    int a[MAXOPS] = {};
    int b[MAXOPS] = {};
    int c[MAXOPS] = {};
};

__host__ __device__ constexpr Ops4 build_ops_cx(int variant) {
    Ops4 ops{};
    PcgCx rng;
    seed_direct_cx(rng, variant >> 1, variant & 1);
    int i = 0;
    while (i < 4 && ops.n < MAXOPS) {
        if (rng.next_double() > 0.3) {
            int kind = (int)rng.lemire32(2);
            int w    = (int)rng.lemire32(3);
            ops.type[ops.n] = 0; ops.a[ops.n] = kind; ops.b[ops.n] = w; ops.c[ops.n] = i;
            ops.n++; i++;
        } else {
            int arr[4] = {0, 1, 2, 3};
            for (int t = 3; t >= 1; t--) {
                int j = (int)rng.random_interval((uint64_t)t);
                int tmp = arr[t]; arr[t] = arr[j]; arr[j] = tmp;
            }
            ops.type[ops.n] = 1; ops.a[ops.n] = arr[0]; ops.b[ops.n] = arr[1]; ops.c[ops.n] = 0;
            ops.n++;
        }
    }
    return ops;
}

// Pauli product (0=I,1=X,2=Y,3=Z): sigma_a*sigma_b = i^k sigma_r
__host__ __device__ constexpr int pmul_h(int a, int b, int& k) {
    if (a == 0) return b;
    if (b == 0) return a;
    if (a == b) return 0;
    int r = 6 - a - b;
    k += (b == (a % 3) + 1) ? 1 : 3;
    return r;
}

// Structural term derivation
struct TermsCx {
    int n[4] = {};
    int ec[4][16] = {};    // e-code: e0|e1<<2|e2<<4|e3<<6, e: 0=I,1=C,2=S
    bool uc[4] = {}, us[4] = {};
};

__host__ __device__ constexpr TermsCx derive_terms_cx(const Ops4& ops) {
    TermsCx t{};
    for (int w = 0; w < 4; w++) {
        for (int path = 0; path < 16; path++) {
            int lets = 3 << (2 * w);
            bool dead = false;
            int rbit = 0;
            for (int g = ops.n - 1; g >= 0 && !dead; g--) {
                if (ops.type[g] == 0) {
                    int P = ops.a[g] + 1;
                    int wi = ops.b[g];
                    int q = (lets >> (2 * wi)) & 3;
                    int take = (path >> rbit) & 1;
                    rbit++;
                    if (q == 0 || q == P) {
                        if (take) dead = true;
                    } else if (take) {
                        int r = 6 - P - q;
                        lets = (lets & ~(3 << (2 * wi))) | (r << (2 * wi));
                    }
                } else {
                    int c = ops.a[g], tt = ops.b[g];
                    int a = (lets >> (2 * c)) & 3;
                    int bb = (lets >> (2 * tt)) & 3;
                    int At = (a == 1 || a == 2) ? 1 : 0;
                    int Bc2 = (bb == 2 || bb == 3) ? 3 : 0;
                    int k = 0;
                    int nc = pmul_h(a, Bc2, k);
                    int nt = pmul_h(At, bb, k);
                    lets = (lets & ~((3 << (2 * c)) | (3 << (2 * tt))))
                         | (nc << (2 * c)) | (nt << (2 * tt));
                }
            }
            if (dead) continue;
            int e[4] = {}, ok = 1;
            for (int wi = 0; wi < 4; wi++) {
                int L = (lets >> (2 * wi)) & 3;
                if (L == 2) { ok = 0; break; }
                e[wi] = (L == 0) ? 0 : ((L == 3) ? 1 : 2);
            }
            if (!ok) continue;
            int ecb = e[0] | (e[1] << 2) | (e[2] << 4) | (e[3] << 6);
            bool found = false;
            for (int jj = 0; jj < t.n[w]; jj++)
                if (t.ec[w][jj] == ecb) { found = true; break; }
            if (!found && t.n[w] < 16) {
                t.ec[w][t.n[w]] = ecb;
                t.n[w]++;
            }
        }
    }
    for (int w = 0; w < 4; w++)
        for (int jj = 0; jj < t.n[w]; jj++)
            for (int wi = 0; wi < 4; wi++) {
                int e = (t.ec[w][jj] >> (2 * wi)) & 3;
                if (e == 1) t.uc[wi] = true;
                if (e == 2) t.us[wi] = true;
            }
    return t;
}

// Per-(wire,path) structural info: liveness, target term, sign, cos/sin masks
struct PathInfo { int live; int term; int neg; int cmask; int smask; };

__host__ __device__ constexpr PathInfo path_info_cx(const Ops4& ops, const TermsCx& t,
                                                    int w, int path) {
    PathInfo pi{0, 0, 0, 0, 0};
    int lets = 3 << (2 * w);
    int rbit = 0;
    for (int g = ops.n - 1; g >= 0; g--) {
        if (ops.type[g] == 0) {
            int P = ops.a[g] + 1;
            int wi = ops.b[g];
            int q = (lets >> (2 * wi)) & 3;
            int take = (path >> rbit) & 1;
            rbit++;
            if (q == 0 || q == P) {
                if (take) return PathInfo{0, 0, 0, 0, 0};
            } else if (!take) {
                pi.cmask |= 1 << ops.c[g];
            } else {
                pi.smask |= 1 << ops.c[g];
                int r = 6 - P - q;
                int qp = (P == 1) ? 3 : P - 1;
                if (q != qp) pi.neg ^= 1;
                lets = (lets & ~(3 << (2 * wi))) | (r << (2 * wi));
            }
        } else {
            int c = ops.a[g], tt = ops.b[g];
            int a = (lets >> (2 * c)) & 3;
            int bb = (lets >> (2 * tt)) & 3;
            int At = (a == 1 || a == 2) ? 1 : 0;
            int Bc2 = (bb == 2 || bb == 3) ? 3 : 0;
            int k = 0;
            int nc = pmul_h(a, Bc2, k);
            int nt = pmul_h(At, bb, k);
            if ((k & 3) == 2) pi.neg ^= 1;
            lets = (lets & ~((3 << (2 * c)) | (3 << (2 * tt))))
                 | (nc << (2 * c)) | (nt << (2 * tt));
        }
    }
    int e[4] = {};
    for (int wi = 0; wi < 4; wi++) {
        int L = (lets >> (2 * wi)) & 3;
        if (L == 2) return PathInfo{0, 0, 0, 0, 0};
        e[wi] = (L == 0) ? 0 : ((L == 3) ? 1 : 2);
    }
    int ecb = e[0] | (e[1] << 2) | (e[2] << 4) | (e[3] << 6);
    for (int jj = 0; jj < t.n[w]; jj++)
        if (t.ec[w][jj] == ecb) { pi.term = jj; pi.live = 1; return pi; }
    return PathInfo{0, 0, 0, 0, 0};
}

__host__ __device__ constexpr uint64_t pack_ec8(const TermsCx& t, int w, int lohalf) {
    uint64_t v = 0;
    for (int j = 0; j < 8; j++) {
        int jj = lohalf * 8 + j;
        if (jj < t.n[w]) v |= ((uint64_t)(t.ec[w][jj] & 0xff)) << (8 * j);
    }
    return v;
}
__host__ __device__ constexpr int pack_ucs(const TermsCx& t) {
    int v = 0;
    for (int w = 0; w < 4; w++) {
        if (t.uc[w]) v |= 1 << w;
        if (t.us[w]) v |= 1 << (4 + w);
    }
    return v;
}

// ---- compile-time constants ----
constexpr int     CXV   = find_variant_cx();
constexpr Ops4    CXOPS = build_ops_cx(CXV < 0 ? 0 : CXV);
constexpr TermsCx CXT   = (CXV >= 0) ? derive_terms_cx(CXOPS) : TermsCx{};
constexpr int CN0 = CXT.n[0], CN1 = CXT.n[1], CN2 = CXT.n[2], CN3 = CXT.n[3];
constexpr uint64_t CA0 = pack_ec8(CXT, 0, 0), CB0 = pack_ec8(CXT, 0, 1);
constexpr uint64_t CA1 = pack_ec8(CXT, 1, 0), CB1 = pack_ec8(CXT, 1, 1);
constexpr uint64_t CA2 = pack_ec8(CXT, 2, 0), CB2 = pack_ec8(CXT, 2, 1);
constexpr uint64_t CA3 = pack_ec8(CXT, 3, 0), CB3 = pack_ec8(CXT, 3, 1);
constexpr int CUCS = pack_ucs(CXT);

// ============================================================================
// Device helpers
// ============================================================================
typedef unsigned long long ull;

__device__ __forceinline__ ull pk2f(float lo, float hi) {
    ull r; asm("mov.b64 %0, {%1, %2};" : "=l"(r) : "f"(lo), "f"(hi)); return r;
}
__device__ __forceinline__ void upk2f(ull v, float& lo, float& hi) {
    asm("mov.b64 {%0, %1}, %2;" : "=f"(lo), "=f"(hi) : "l"(v));
}
__device__ __forceinline__ ull fma2_(ull a, ull b, ull c) {
    ull d; asm("fma.rn.f32x2 %0, %1, %2, %3;" : "=l"(d) : "l"(a), "l"(b), "l"(c)); return d;
}
__device__ __forceinline__ ull mul2_(ull a, ull b) {
    ull d; asm("mul.rn.f32x2 %0, %1, %2;" : "=l"(d) : "l"(a), "l"(b)); return d;
}
__device__ __forceinline__ ull add2_(ull a, ull b) {
    ull d; asm("add.rn.f32x2 %0, %1, %2;" : "=l"(d) : "l"(a), "l"(b)); return d;
}

template <int EC>
__device__ __forceinline__ ull prod_ec(ull C0, ull S0, ull C1, ull S1,
                                       ull C2, ull S2, ull C3, ull S3) {
    constexpr int e0 = EC & 3, e1 = (EC >> 2) & 3, e2 = (EC >> 4) & 3, e3 = (EC >> 6) & 3;
    ull u = 0x3f8000003f800000ULL;
    if constexpr (e0 == 1) u = C0; else if constexpr (e0 == 2) u = S0;
    constexpr bool h0 = (e0 != 0);
    if constexpr (e1 != 0) { ull f = (e1 == 1) ? C1 : S1; if constexpr (h0) u = mul2_(u, f); else u = f; }
    constexpr bool h1 = h0 || (e1 != 0);
    if constexpr (e2 != 0) { ull f = (e2 == 1) ? C2 : S2; if constexpr (h1) u = mul2_(u, f); else u = f; }
    constexpr bool h2 = h1 || (e2 != 0);
    if constexpr (e3 != 0) { ull f = (e3 == 1) ? C3 : S3; if constexpr (h2) u = mul2_(u, f); else u = f; }
    return u;
}

// Per-thread coefficient path contribution (fully constant-folded)
template <int W, int P, int NT>
__device__ __forceinline__ void add_path(float (&cf)[NT],
                                         const float (&cv)[4], const float (&sv)[4]) {
    constexpr PathInfo pi = path_info_cx(CXOPS, CXT, W, P);
    if constexpr (pi.live != 0 && pi.term < NT) {
        float v = 1.0f;
        if constexpr (pi.cmask & 1) v *= cv[0];
        if constexpr (pi.cmask & 2) v *= cv[1];
        if constexpr (pi.cmask & 4) v *= cv[2];
        if constexpr (pi.cmask & 8) v *= cv[3];
        if constexpr (pi.smask & 1) v *= sv[0];
        if constexpr (pi.smask & 2) v *= sv[1];
        if constexpr (pi.smask & 4) v *= sv[2];
        if constexpr (pi.smask & 8) v *= sv[3];
        if constexpr (pi.neg) cf[pi.term] -= v; else cf[pi.term] += v;
    }
}

// ============================================================================
// FUSED KERNEL — barrier-free, smem-free: every thread derives the 6 coefs
// ============================================================================
#define NBLK 444
#define UPB  591   // 444*591 = 262404 >= 262144 units

template <int N0, int N1, int N2, int N3,
          ull A0, ull B0, ull A1, ull B1, ull A2, ull B2, ull A3, ull B3, int UCS>
__global__ void __launch_bounds__(512, 3) quanv_cx(const float* __restrict__ rp,
                                                   const float4* __restrict__ x4,
                                                   float4* __restrict__ out4) {
    const int tx = threadIdx.x;
    const int ustart = blockIdx.x * UPB;
    const int uend   = min(ustart + UPB, 262144);
    const int u0 = ustart + tx;
    const bool v0 = (u0 < uend);

    // ---- early loads for unit 0 ----
    float4 f00, f01, f10, f11;
    if (v0) {
        int r00 = ((u0 >> 14) << 16) + (((u0 >> 9) & 31) << 11) + (((u0 >> 4) & 31) << 5) + (u0 & 15);
        f00 = x4[r00];
        f01 = x4[r00 + 16];
        f10 = x4[r00 + 1024];
        f11 = x4[r00 + 1040];
    }

    // ---- per-thread coefficient derivation (~50 cycles, no communication) ----
    float cv[4], sv[4];
#pragma unroll
    for (int i = 0; i < 4; i++)
        __sincosf(__ldg(&rp[i]), &sv[i], &cv[i]);

    float cf0[N0 > 0 ? N0 : 1] = {};
    float cf1[N1 > 0 ? N1 : 1] = {};
    float cf2[N2 > 0 ? N2 : 1] = {};
    float cf3[N3 > 0 ? N3 : 1] = {};
#define ADDP_W(W, CF) \
    add_path<W, 0>(CF, cv, sv);  add_path<W, 1>(CF, cv, sv);  add_path<W, 2>(CF, cv, sv);  add_path<W, 3>(CF, cv, sv); \
    add_path<W, 4>(CF, cv, sv);  add_path<W, 5>(CF, cv, sv);  add_path<W, 6>(CF, cv, sv);  add_path<W, 7>(CF, cv, sv); \
    add_path<W, 8>(CF, cv, sv);  add_path<W, 9>(CF, cv, sv);  add_path<W, 10>(CF, cv, sv); add_path<W, 11>(CF, cv, sv); \
    add_path<W, 12>(CF, cv, sv); add_path<W, 13>(CF, cv, sv); add_path<W, 14>(CF, cv, sv); add_path<W, 15>(CF, cv, sv);
    ADDP_W(0, cf0)
    ADDP_W(1, cf1)
    ADDP_W(2, cf2)
    ADDP_W(3, cf3)
#undef ADDP_W

    // duplicated-pair packed coefficients
    ull cw0[N0 > 0 ? N0 : 1], cw1[N1 > 0 ? N1 : 1], cw2[N2 > 0 ? N2 : 1], cw3[N3 > 0 ? N3 : 1];
#pragma unroll
    for (int j = 0; j < N0; j++) { uint32_t u = __float_as_uint(cf0[j]); cw0[j] = (ull)u | ((ull)u << 32); }
#pragma unroll
    for (int j = 0; j < N1; j++) { uint32_t u = __float_as_uint(cf1[j]); cw1[j] = (ull)u | ((ull)u << 32); }
#pragma unroll
    for (int j = 0; j < N2; j++) { uint32_t u = __float_as_uint(cf2[j]); cw2[j] = (ull)u | ((ull)u << 32); }
#pragma unroll
    for (int j = 0; j < N3; j++) { uint32_t u = __float_as_uint(cf3[j]); cw3[j] = (ull)u | ((ull)u << 32); }

    constexpr bool uc0 = UCS & 1, uc1 = UCS & 2, uc2 = UCS & 4, uc3 = UCS & 8;
    constexpr bool us0 = UCS & 16, us1 = UCS & 32, us2 = UCS & 64, us3 = UCS & 128;

    // ---- per-unit body ----
    auto body = [&](int u, float4 g00, float4 g01, float4 g10, float4 g11) {
        const float PI = 3.14159265358979323846f;
        ull C0 = 0, S0 = 0, C1 = 0, S1 = 0, C2 = 0, S2 = 0, C3 = 0, S3 = 0;
        float sa, ca, sb, cb;

#define TRIG_W(UC, US, XLO, XHI, CV, SV) \
        if constexpr (UC && US) { \
            __sincosf(PI * (XLO), &sa, &ca); __sincosf(PI * (XHI), &sb, &cb); \
            CV = pk2f(ca, cb); SV = pk2f(sa, sb); \
        } else if constexpr (UC) { \
            CV = pk2f(__cosf(PI * (XLO)), __cosf(PI * (XHI))); \
        } else if constexpr (US) { \
            SV = pk2f(__sinf(PI * (XLO)), __sinf(PI * (XHI))); \
        }
        TRIG_W(uc0, us0, g00.x, g00.z, C0, S0)
        TRIG_W(uc1, us1, g11.x, g11.z, C1, S1)
        TRIG_W(uc2, us2, g01.y, g01.w, C2, S2)
        TRIG_W(uc3, us3, g10.y, g10.w, C3, S3)
#undef TRIG_W

        ull acc0 = 0, acc1 = 0, acc2 = 0, acc3 = 0;

#define DO_T(W, J, NN, AA, BB, ACC, ARR) \
        if constexpr (J < NN) { \
            constexpr int ec_ = (int)(((J < 8) ? (AA >> (8 * J)) : (BB >> (8 * (J - 8)))) & 255ULL); \
            ACC = fma2_(prod_ec<ec_>(C0, S0, C1, S1, C2, S2, C3, S3), ARR[J], ACC); \
        }
#define DO_W(W, NN, AA, BB, ACC, ARR) \
        DO_T(W, 0, NN, AA, BB, ACC, ARR)  DO_T(W, 1, NN, AA, BB, ACC, ARR)  DO_T(W, 2, NN, AA, BB, ACC, ARR)  DO_T(W, 3, NN, AA, BB, ACC, ARR) \
        DO_T(W, 4, NN, AA, BB, ACC, ARR)  DO_T(W, 5, NN, AA, BB, ACC, ARR)  DO_T(W, 6, NN, AA, BB, ACC, ARR)  DO_T(W, 7, NN, AA, BB, ACC, ARR) \
        DO_T(W, 8, NN, AA, BB, ACC, ARR)  DO_T(W, 9, NN, AA, BB, ACC, ARR)  DO_T(W, 10, NN, AA, BB, ACC, ARR) DO_T(W, 11, NN, AA, BB, ACC, ARR) \
        DO_T(W, 12, NN, AA, BB, ACC, ARR) DO_T(W, 13, NN, AA, BB, ACC, ARR) DO_T(W, 14, NN, AA, BB, ACC, ARR) DO_T(W, 15, NN, AA, BB, ACC, ARR)

        DO_W(0, N0, A0, B0, acc0, cw0)
        DO_W(1, N1, A1, B1, acc1, cw1)
        DO_W(2, N2, A2, B2, acc2, cw2)
        DO_W(3, N3, A3, B3, acc3, cw3)
#undef DO_W
#undef DO_T

        float a0l, a0h, a1l, a1h, a2l, a2h, a3l, a3h;
        upk2f(acc0, a0l, a0h); upk2f(acc1, a1l, a1h);
        upk2f(acc2, a2l, a2h); upk2f(acc3, a3l, a3h);
        __stcs(&out4[2 * u],     make_float4(a0l, a1l, a2l, a3l));
        __stcs(&out4[2 * u + 1], make_float4(a0h, a1h, a2h, a3h));
    };

    if (v0) body(u0, f00, f01, f10, f11);

    // overhang units (UPB-512 = 79) on high-tx threads
    if (tx >= 512 - (UPB - 512)) {
        int u1 = ustart + (UPB - 512) + tx;
        if (u1 < uend) {
            int r00 = ((u1 >> 14) << 16) + (((u1 >> 9) & 31) << 11) + (((u1 >> 4) & 31) << 5) + (u1 & 15);
            float4 h00 = x4[r00];
            float4 h01 = x4[r00 + 16];
            float4 h10 = x4[r00 + 1024];
            float4 h11 = x4[r00 + 1040];
            body(u1, h00, h01, h10, h11);
        }
    }
}

// ============================================================================
// DENSE FALLBACK (proven R8 kernels)
// ============================================================================
__device__ float4 g_coef4[162];

__device__ __forceinline__ float2 cmulf(float2 a, float2 b) {
    return make_float2(a.x * b.x - a.y * b.y, a.x * b.y + a.y * b.x);
}
__device__ __forceinline__ float2 caddf(float2 a, float2 b) {
    return make_float2(a.x + b.x, a.y + b.y);
}
__device__ __forceinline__ float Bc(int jb, int kb, int e) {
    if (jb != kb) return (e == 2) ? 0.5f : 0.0f;
    if (e == 2) return 0.0f;
    if (e == 0) return 0.5f;
    return jb ? -0.5f : 0.5f;
}

__global__ void quanv_setup(const float* __restrict__ rp, Ops4 ops) {
    __shared__ float2 U[16][16];
    __shared__ float ReM[4][16][16];
    __shared__ float G[4][9][16];
    int tid = threadIdx.x;

    if (tid < 16) {
        int col = tid;
        for (int m = 0; m < 16; m++)
            U[m][col] = make_float2(m == col ? 1.0f : 0.0f, 0.0f);
        for (int o = 0; o < ops.n; o++) {
            if (ops.type[o] == 0) {
                float th = rp[ops.c[o]];
                float ch = cosf(0.5f * th), sh = sinf(0.5f * th);
                float2 R00, R01, R10, R11;
                int kind = ops.a[o];
                if (kind == 0) {
                    R00 = make_float2(ch, 0); R11 = R00;
                    R01 = make_float2(0, -sh); R10 = R01;
                } else if (kind == 1) {
                    R00 = make_float2(ch, 0); R11 = R00;
                    R01 = make_float2(-sh, 0); R10 = make_float2(sh, 0);
                } else {
                    R00 = make_float2(ch, -sh); R11 = make_float2(ch, sh);
                    R01 = make_float2(0, 0);    R10 = make_float2(0, 0);
                }
                int bit = 1 << (3 - ops.b[o]);
                for (int m = 0; m < 16; m++) {
                    if (!(m & bit)) {
                        float2 x0 = U[m][col], x1 = U[m | bit][col];
                        U[m][col]       = caddf(cmulf(R00, x0), cmulf(R01, x1));
                        U[m | bit][col] = caddf(cmulf(R10, x0), cmulf(R11, x1));
                    }
                }
            } else {
                int cb = 1 << (3 - ops.a[o]);
                int tb = 1 << (3 - ops.b[o]);
                for (int m = 0; m < 16; m++) {
                    if ((m & cb) && !(m & tb)) {
                        float2 tmp = U[m][col];
                        U[m][col] = U[m | tb][col];
                        U[m | tb][col] = tmp;
                    }
                }
            }
        }
    }
    __syncthreads();

    for (int e = tid; e < 1024; e += blockDim.x) {
        int w = e >> 8, jk = e & 255, jj = jk >> 4, kk = jk & 15;
        int sbit = 1 << (3 - w);
        float sum = 0.0f;
        for (int m = 0; m < 16; m++) {
            float2 uj = U[m][jj], uk = U[m][kk];
            float re = uj.x * uk.x + uj.y * uk.y;
            sum += (m & sbit) ? -re : re;
        }
        ReM[w][jj][kk] = sum;
    }
    __syncthreads();

    for (int e = tid; e < 576; e += blockDim.x) {
        int w = e / 144, r = e % 144, p = r / 16, lk = r % 16;
        int jl = lk >> 2, kl = lk & 3;
        int e0 = p / 3, e1 = p % 3;
        float sum = 0.0f;
        for (int jh = 0; jh < 4; jh++)
            for (int kh = 0; kh < 4; kh++) {
                float w01 = Bc(jh >> 1, kh >> 1, e0) * Bc(jh & 1, kh & 1, e1);
                if (w01 != 0.0f)
                    sum += w01 * ReM[w][jh * 4 + jl][kh * 4 + kl];
            }
        G[w][p][lk] = sum;
    }
    __syncthreads();

    for (int m = tid; m < 81; m += blockDim.x) {
        int p = m / 9, q = m % 9;
        int e2 = q / 3, e3 = q % 3;
        float cw[4];
        for (int w = 0; w < 4; w++) {
            float sum = 0.0f;
            for (int jl = 0; jl < 4; jl++)
                for (int kl = 0; kl < 4; kl++) {
                    float w23 = Bc(jl >> 1, kl >> 1, e2) * Bc(jl & 1, kl & 1, e3);
                    if (w23 != 0.0f)
                        sum += w23 * G[w][p][jl * 4 + kl];
                }
            cw[w] = sum;
        }
        g_coef4[2 * m]     = make_float4(cw[0], cw[0], cw[1], cw[1]);
        g_coef4[2 * m + 1] = make_float4(cw[2], cw[2], cw[3], cw[3]);
    }
}

__global__ void __launch_bounds__(256) quanv_main(const float4* __restrict__ x4,
                                                  float4* __restrict__ out4) {
    __shared__ ulonglong2 shc[162];
    if (threadIdx.x < 162) {
        const ulonglong2* gc = reinterpret_cast<const ulonglong2*>(g_coef4);
        shc[threadIdx.x] = gc[threadIdx.x];
    }
    __syncthreads();

    int tid = blockIdx.x * 256 + threadIdx.x;
    int r00 = ((tid >> 14) << 16) + (((tid >> 9) & 31) << 11) + (((tid >> 4) & 31) << 5) + (tid & 15);
    float4 f00 = __ldcs(&x4[r00]);
    float4 f01 = __ldcs(&x4[r00 + 16]);
    float4 f10 = __ldcs(&x4[r00 + 1024]);
    float4 f11 = __ldcs(&x4[r00 + 1040]);

    const float PI = 3.14159265358979323846f;
    float s0, c0, s1, c1;
    ull C0, S0, C1, S1, C2, S2, C3, S3;
    __sincosf(PI * f00.x, &s0, &c0); __sincosf(PI * f00.z, &s1, &c1);
    C0 = pk2f(c0, c1); S0 = pk2f(s0, s1);
    __sincosf(PI * f11.x, &s0, &c0); __sincosf(PI * f11.z, &s1, &c1);
    C1 = pk2f(c0, c1); S1 = pk2f(s0, s1);
    __sincosf(PI * f01.y, &s0, &c0); __sincosf(PI * f01.w, &s1, &c1);
    C2 = pk2f(c0, c1); S2 = pk2f(s0, s1);
    __sincosf(PI * f10.y, &s0, &c0); __sincosf(PI * f10.w, &s1, &c1);
    C3 = pk2f(c0, c1); S3 = pk2f(s0, s1);

    ull v01[9], v23[9];
    v01[0] = 0; v23[0] = 0;
    v01[1] = C1; v01[2] = S1; v01[3] = C0;
    v01[4] = mul2_(C0, C1); v01[5] = mul2_(C0, S1);
    v01[6] = S0; v01[7] = mul2_(S0, C1); v01[8] = mul2_(S0, S1);
    v23[1] = C3; v23[2] = S3; v23[3] = C2;
    v23[4] = mul2_(C2, C3); v23[5] = mul2_(C2, S3);
    v23[6] = S2; v23[7] = mul2_(S2, C3); v23[8] = mul2_(S2, S3);

    ull acc0 = 0, acc1 = 0, acc2 = 0, acc3 = 0;

#pragma unroll
    for (int p = 0; p < 9; p++) {
#pragma unroll
        for (int q = 0; q < 9; q++) {
            int m = p * 9 + q;
            ulonglong2 ca = shc[2 * m];
            ulonglong2 cb = shc[2 * m + 1];
            if (p == 0 && q == 0) {
                acc0 = add2_(acc0, ca.x);
                acc1 = add2_(acc1, ca.y);
                acc2 = add2_(acc2, cb.x);
                acc3 = add2_(acc3, cb.y);
            } else {
                ull tpq = (p == 0) ? v23[q] : ((q == 0) ? v01[p] : mul2_(v01[p], v23[q]));
                acc0 = fma2_(tpq, ca.x, acc0);
                acc1 = fma2_(tpq, ca.y, acc1);
                acc2 = fma2_(tpq, cb.x, acc2);
                acc3 = fma2_(tpq, cb.y, acc3);
            }
        }
    }

    float a0l, a0h, a1l, a1h, a2l, a2h, a3l, a3h;
    upk2f(acc0, a0l, a0h); upk2f(acc1, a1l, a1h);
    upk2f(acc2, a2l, a2h); upk2f(acc3, a3l, a3h);
    out4[2 * tid]     = make_float4(a0l, a1l, a2l, a3l);
    out4[2 * tid + 1] = make_float4(a0h, a1h, a2h, a3h);
}

// ============================================================================
// Launch
// ============================================================================
static bool terms_equal(const TermsCx& a, const TermsCx& b) {
    for (int w = 0; w < 4; w++) {
        if (a.n[w] != b.n[w]) return false;
        if (a.uc[w] != b.uc[w] || a.us[w] != b.us[w]) return false;
        for (int j = 0; j < a.n[w]; j++)
            if (a.ec[w][j] != b.ec[w][j]) return false;
    }
    return true;
}

extern "C" void kernel_launch(void* const* d_in, const int* in_sizes, int n_in,
                              void* d_out, int out_size) {
    const float* x  = (const float*)d_in[0];
    const float* rp = (const float*)d_in[1];
    if (n_in >= 2 && in_sizes[0] == 4) {
        const float* tmp = x; x = rp; rp = tmp;
    }

    int rv = find_variant_cx();
    if (rv < 0) {
        fputs("DIAG rng verification failed\n", stderr);
        fflush(stderr);
        return;
    }
    Ops4 rops = build_ops_cx(rv);
    TermsCx rt_ = derive_terms_cx(rops);

    bool cx_ok = (CXV >= 0) && (rv == CXV) && terms_equal(rt_, CXT);

    if (cx_ok) {
        quanv_cx<CN0, CN1, CN2, CN3, CA0, CB0, CA1, CB1, CA2, CB2, CA3, CB3, CUCS>
            <<<NBLK, 512>>>(rp, (const float4*)x, (float4*)d_out);
    } else {
        quanv_setup<<<1, 512>>>(rp, rops);
        quanv_main<<<1024, 256>>>((const float4*)x, (float4*)d_out);
    }
}